// round 15
// baseline (speedup 1.0000x reference)
#include <cuda_runtime.h>
#include <cuda_bf16.h>
#include <math.h>
#include <stdint.h>

#define BATCH 8
#define NLAT  256
#define SEQ   4096
#define DIM   1024
#define HEADS 16
#define DHEAD 64
#define INNER 1024
#define EPSLN 1e-5f
#define BH    (BATCH * HEADS)     // 128

// ---- GEMM geometry
#define GM     (BATCH * SEQ)      // 32768
#define GN     (2 * INNER)        // 2048
#define MT     (GM / 128)         // 256 m tiles (kv)
#define NT     (GN / 128)         // 16 n tiles (kv)
#define KCH    (DIM / 64)         // 16 k chunks of 64
#define BLK    16384              // one 128row x 128B swizzled block
#define NSTG   3
#define STG_BYTES (4 * BLK)       // Ah|Al|Bh|Bl = 64KB per stage
#define OFF_STG  1024

// ---------------- scratch (device globals: no runtime allocation) ----------
__device__ uint4 g_A[(size_t)MT * KCH * 2 * BLK / 16];        // 134 MB ctx split-bf16
__device__ uint4 g_B[(size_t)NT * KCH * 2 * BLK / 16];        //   8 MB Wkv split
__device__ uint4 g_Aq[(size_t)16 * KCH * 2 * BLK / 16];       //   8 MB lat split
__device__ uint4 g_Bq[(size_t)8 * KCH * 2 * BLK / 16];        //   4 MB Wq split
__device__ uint4 g_Bo[(size_t)8 * KCH * 2 * BLK / 16];        //   4 MB Wo split
__device__ uint4 g_obf[(size_t)16 * KCH * 2 * BLK / 16];      //   8 MB attn-out split
__device__ uint4 g_qbf[(size_t)BH * 2 * 256 * 128 / 16];      //   8 MB Q hi/lo swizzled
__device__ uint4 g_kbf[(size_t)BH * 64 * 16384 / 16];         // 128 MB K hi/lo (roped)
__device__ uint4 g_vbf[(size_t)BH * 64 * 16384 / 16];         // 128 MB V^T hi/lo

// ---------------- PTX helpers ----------------------------------------------
__device__ __forceinline__ uint32_t smem_u32(const void* p) {
    uint32_t a;
    asm("{ .reg .u64 t; cvta.to.shared.u64 t, %1; cvt.u32.u64 %0, t; }"
        : "=r"(a) : "l"(p));
    return a;
}
__device__ __forceinline__ void mbar_init(uint32_t m, uint32_t cnt) {
    asm volatile("mbarrier.init.shared.b64 [%0], %1;" :: "r"(m), "r"(cnt) : "memory");
}
__device__ __forceinline__ void mbar_expect(uint32_t m, uint32_t bytes) {
    asm volatile("mbarrier.arrive.expect_tx.shared.b64 _, [%0], %1;"
                 :: "r"(m), "r"(bytes) : "memory");
}
__device__ __forceinline__ void mbar_wait(uint32_t m, int ph) {
    asm volatile(
        "{\n\t.reg .pred P;\n\t"
        "W%=:\n\t"
        "mbarrier.try_wait.parity.shared.b64 P, [%0], %1;\n\t"
        "@!P bra W%=;\n\t}"
        :: "r"(m), "r"(ph) : "memory");
}
__device__ __forceinline__ void bulk_g2s(uint32_t dst, const void* src,
                                         uint32_t bytes, uint32_t mbar) {
    asm volatile(
        "cp.async.bulk.shared::cluster.global.mbarrier::complete_tx::bytes "
        "[%0], [%1], %2, [%3];"
        :: "r"(dst), "l"(src), "r"(bytes), "r"(mbar) : "memory");
}
__device__ __forceinline__ void ldmx4(uint32_t* r, uint32_t addr) {
    asm volatile("ldmatrix.sync.aligned.m8n8.x4.shared.b16 {%0,%1,%2,%3}, [%4];"
                 : "=r"(r[0]), "=r"(r[1]), "=r"(r[2]), "=r"(r[3]) : "r"(addr));
}
__device__ __forceinline__ void mma16816(float* c, const uint32_t* a,
                                         uint32_t b0, uint32_t b1) {
    asm volatile(
        "mma.sync.aligned.m16n8k16.row.col.f32.bf16.bf16.f32 "
        "{%0,%1,%2,%3}, {%4,%5,%6,%7}, {%8,%9}, {%0,%1,%2,%3};"
        : "+f"(c[0]), "+f"(c[1]), "+f"(c[2]), "+f"(c[3])
        : "r"(a[0]), "r"(a[1]), "r"(a[2]), "r"(a[3]), "r"(b0), "r"(b1));
}
__device__ __forceinline__ void split2(float a, float b, uint32_t& hi, uint32_t& lo) {
    __nv_bfloat16 ha = __float2bfloat16(a), hb = __float2bfloat16(b);
    float ra = a - __bfloat162float(ha), rb = b - __bfloat162float(hb);
    __nv_bfloat16 la = __float2bfloat16(ra), lb = __float2bfloat16(rb);
    hi = (uint32_t)__bfloat16_as_ushort(ha) | ((uint32_t)__bfloat16_as_ushort(hb) << 16);
    lo = (uint32_t)__bfloat16_as_ushort(la) | ((uint32_t)__bfloat16_as_ushort(lb) << 16);
}

// ---------------- shared split-bf16 mma mainloop ----------------------------
extern __shared__ char dyn_smem[];

__device__ __forceinline__ void mma_tile_mainloop(
    const char* __restrict__ Ab, const char* __restrict__ Bb, const int kch,
    const uint32_t sb, float (&acc)[2][8][4])
{
    const int t = threadIdx.x;
    const int w = t >> 5, lane = t & 31;
    const int wm = w & 3, wn = w >> 2;          // 4 x 2 warp grid

    if (t == 0) {
        #pragma unroll
        for (int i = 0; i < NSTG; i++) mbar_init(sb + 8 * i, 1);
    }
    __syncthreads();
    asm volatile("fence.proxy.async.shared::cta;" ::: "memory");

    if (t == 0) {
        #pragma unroll
        for (int c = 0; c < NSTG; c++) {
            uint32_t st = sb + OFF_STG + c * STG_BYTES;
            mbar_expect(sb + 8 * c, STG_BYTES);
            bulk_g2s(st,           Ab + (size_t)c * 2 * BLK, 2 * BLK, sb + 8 * c);
            bulk_g2s(st + 2 * BLK, Bb + (size_t)c * 2 * BLK, 2 * BLK, sb + 8 * c);
        }
    }

    const int l15 = lane & 15;
    const uint32_t kb16 = (uint32_t)(lane & 16);
    const uint32_t mask = (uint32_t)((lane & 7) << 4);
    uint32_t aoff[2], boff[4];
    #pragma unroll
    for (int mi = 0; mi < 2; mi++) aoff[mi] = (uint32_t)((wm * 32 + mi * 16 + l15) * 128);
    #pragma unroll
    for (int p = 0; p < 4; p++)    boff[p]  = (uint32_t)((wn * 64 + p * 16 + l15) * 128);

    #pragma unroll
    for (int mi = 0; mi < 2; mi++)
        #pragma unroll
        for (int ni = 0; ni < 8; ni++)
            #pragma unroll
            for (int q = 0; q < 4; q++) acc[mi][ni][q] = 0.f;

    int ph[NSTG] = {0, 0, 0};

    for (int kc = 0; kc < kch; kc++) {
        const int s = kc % NSTG;
        mbar_wait(sb + 8 * s, ph[s]); ph[s] ^= 1;
        const uint32_t base = sb + OFF_STG + s * STG_BYTES;

        #pragma unroll
        for (int ks = 0; ks < 4; ks++) {
            const uint32_t kx = ((uint32_t)(ks * 32) + kb16) ^ mask;
            uint32_t ah[2][4], al[2][4], bh[4][4], bl[4][4];
            #pragma unroll
            for (int mi = 0; mi < 2; mi++) {
                ldmx4(ah[mi], base + aoff[mi] + kx);
                ldmx4(al[mi], base + BLK + aoff[mi] + kx);
            }
            #pragma unroll
            for (int p = 0; p < 4; p++) {
                ldmx4(bh[p], base + 2 * BLK + boff[p] + kx);
                ldmx4(bl[p], base + 3 * BLK + boff[p] + kx);
            }
            #pragma unroll
            for (int mi = 0; mi < 2; mi++)
                #pragma unroll
                for (int p = 0; p < 4; p++) {
                    mma16816(acc[mi][2 * p + 0], ah[mi], bh[p][0], bh[p][2]);
                    mma16816(acc[mi][2 * p + 1], ah[mi], bh[p][1], bh[p][3]);
                    mma16816(acc[mi][2 * p + 0], ah[mi], bl[p][0], bl[p][2]);
                    mma16816(acc[mi][2 * p + 1], ah[mi], bl[p][1], bl[p][3]);
                    mma16816(acc[mi][2 * p + 0], al[mi], bh[p][0], bh[p][2]);
                    mma16816(acc[mi][2 * p + 1], al[mi], bh[p][1], bh[p][3]);
                }
        }
        __syncthreads();
        const int nxt = kc + NSTG;
        if (t == 0 && nxt < kch) {
            mbar_expect(sb + 8 * s, STG_BYTES);
            bulk_g2s(base,           Ab + (size_t)nxt * 2 * BLK, 2 * BLK, sb + 8 * s);
            bulk_g2s(base + 2 * BLK, Bb + (size_t)nxt * 2 * BLK, 2 * BLK, sb + 8 * s);
        }
    }
}

// -------- LayerNorm (warp-per-row) fused with split-bf16 A-prep -------------
__global__ __launch_bounds__(256) void ln_prep_kernel(
    const float* __restrict__ x, const float* __restrict__ gam,
    const float* __restrict__ bet, uint4* __restrict__ dstb)
{
    const int wid = threadIdx.x >> 5, lane = threadIdx.x & 31;
    const int row = blockIdx.x * 8 + wid;
    const float4* xr = (const float4*)(x + (size_t)row * DIM);

    float4 v[8];
    float s = 0.f;
    #pragma unroll
    for (int i = 0; i < 8; i++) {
        v[i] = xr[i * 32 + lane];
        s += v[i].x + v[i].y + v[i].z + v[i].w;
    }
    #pragma unroll
    for (int off = 16; off; off >>= 1) s += __shfl_xor_sync(0xffffffffu, s, off);
    const float mu = s * (1.0f / DIM);

    float s2 = 0.f;
    #pragma unroll
    for (int i = 0; i < 8; i++) {
        v[i].x -= mu; v[i].y -= mu; v[i].z -= mu; v[i].w -= mu;
        s2 += v[i].x * v[i].x + v[i].y * v[i].y + v[i].z * v[i].z + v[i].w * v[i].w;
    }
    #pragma unroll
    for (int off = 16; off; off >>= 1) s2 += __shfl_xor_sync(0xffffffffu, s2, off);
    const float rs = rsqrtf(s2 * (1.0f / DIM) + EPSLN);

    const int mt = row >> 7, r = row & 127;
    char* dst0 = (char*)dstb + (size_t)(mt * KCH) * 2 * BLK;
    #pragma unroll
    for (int i = 0; i < 8; i++) {
        const int slot = i * 32 + lane;          // float4 slot 0..255
        const float4 gg = ((const float4*)gam)[slot];
        const float4 bb = ((const float4*)bet)[slot];
        const float o0 = v[i].x * rs * gg.x + bb.x;
        const float o1 = v[i].y * rs * gg.y + bb.y;
        const float o2 = v[i].z * rs * gg.z + bb.z;
        const float o3 = v[i].w * rs * gg.w + bb.w;
        uint32_t h0, l0, h1, l1;
        split2(o0, o1, h0, l0);
        split2(o2, o3, h1, l1);
        const int chunk = slot >> 4;
        const int c = (slot & 15) * 4;
        uint32_t bo = (uint32_t)(r * 128 + c * 2);
        uint32_t sw = bo ^ ((bo >> 3) & 0x70);
        char* dst = dst0 + (size_t)chunk * 2 * BLK + sw;
        *(uint2*)dst = make_uint2(h0, h1);
        *(uint2*)(dst + BLK) = make_uint2(l0, l1);
    }
}

// -------- all 3 weight preps in one launch: grid (KCH, 32) ------------------
__global__ __launch_bounds__(256) void wprep_all_kernel(
    const float* __restrict__ Wq, const float* __restrict__ Wkv,
    const float* __restrict__ Wo)
{
    __shared__ float ws[64][132];     // 132-float pitch: 528B = 33x16, aligned
    const int by = blockIdx.y;
    const float* W;
    uint4* dstb;
    int N, nt;
    if (by < 8)       { W = Wq;  dstb = g_Bq; N = INNER; nt = by; }
    else if (by < 24) { W = Wkv; dstb = g_B;  N = GN;    nt = by - 8; }
    else              { W = Wo;  dstb = g_Bo; N = DIM;   nt = by - 24; }

    const int chunk = blockIdx.x;     // 0..15 (64 k-values each)
    const int t = threadIdx.x;
    {
        const int rr = t >> 5;        // 0..7
        const int cc = (t & 31) * 4;
        #pragma unroll
        for (int i = 0; i < 8; i++) {
            const int k = chunk * 64 + rr + i * 8;
            *(float4*)&ws[rr + i * 8][cc] =
                *(const float4*)&W[(size_t)k * N + nt * 128 + cc];
        }
    }
    __syncthreads();
    const int n = t & 127, sel = t >> 7;
    char* dst = (char*)dstb + ((size_t)(nt * KCH + chunk) * 2) * BLK + sel * BLK;
    #pragma unroll
    for (int j = 0; j < 8; j++) {
        uint32_t outv[4];
        #pragma unroll
        for (int kk = 0; kk < 4; kk++) {
            const int k2 = j * 8 + kk * 2;
            uint32_t hi, lo;
            split2(ws[k2][n], ws[k2 + 1][n], hi, lo);
            outv[kk] = sel ? lo : hi;
        }
        uint32_t bo = (uint32_t)(n * 128 + 16 * j);
        uint32_t sw = bo ^ ((bo >> 3) & 0x70);
        *(uint4*)(dst + sw) = make_uint4(outv[0], outv[1], outv[2], outv[3]);
    }
}

// -------- fused kv + q GEMM --------------------------------------------------
// grid (16, 272): by<256 -> kv tile (bx n-tile, by m-tile)
//                 by>=256 -> q tile (qy = by-256 in 0..15; bx<8 else no-op)
__global__ __launch_bounds__(256) void kvq_mma_kernel(
    const float* __restrict__ cosb, const float* __restrict__ sinb)
{
    const uint32_t sb = smem_u32(dyn_smem);
    const int t = threadIdx.x, w = t >> 5, lane = t & 31;
    const int wm = w & 3, wn = w >> 2, g = lane >> 2, tig = lane & 3;
    const int bx = blockIdx.x, by = blockIdx.y;

    if (by >= 256) {
        // ================= q projection path ================================
        if (bx >= 8) return;
        const int qy = by - 256;
        float acc[2][8][4];
        mma_tile_mainloop((const char*)g_Aq + (size_t)qy * KCH * 2 * BLK,
                          (const char*)g_Bq + (size_t)bx * KCH * 2 * BLK,
                          KCH, sb, acc);
        const int h = bx * 2 + wn;
        #pragma unroll
        for (int mi = 0; mi < 2; mi++) {
            const int grow = qy * 128 + wm * 32 + mi * 16 + g;
            const int b = grow >> 8, n = grow & 255;
            char* base = (char*)g_qbf + (size_t)(b * 16 + h) * 65536;
            #pragma unroll
            for (int ni = 0; ni < 8; ni++) {
                uint32_t hi, lo;
                split2(acc[mi][ni][0] * 0.125f, acc[mi][ni][1] * 0.125f, hi, lo);
                uint32_t bo = (uint32_t)(n * 128 + 16 * ni + 4 * tig);
                uint32_t sw = bo ^ ((bo >> 3) & 0x70);
                *(uint32_t*)(base + sw) = hi;
                *(uint32_t*)(base + 32768 + sw) = lo;
                split2(acc[mi][ni][2] * 0.125f, acc[mi][ni][3] * 0.125f, hi, lo);
                uint32_t bo2 = (uint32_t)((n + 8) * 128 + 16 * ni + 4 * tig);
                uint32_t sw2 = bo2 ^ ((bo2 >> 3) & 0x70);
                *(uint32_t*)(base + sw2) = hi;
                *(uint32_t*)(base + 32768 + sw2) = lo;
            }
        }
        return;
    }

    // ================= kv projection path ===================================
    float acc[2][8][4];
    mma_tile_mainloop((const char*)g_A + (size_t)by * KCH * 2 * BLK,
                      (const char*)g_B + (size_t)bx * KCH * 2 * BLK, KCH, sb, acc);

    if (bx < 8) {
        // ---- K columns: RoPE in registers, write g_kbf swizzled hi/lo ----
        const int h = bx * 2 + wn;
        #pragma unroll
        for (int mi = 0; mi < 2; mi++) {
            const int row0 = by * 128 + wm * 32 + mi * 16 + g;
            const int b = row0 >> 12;
            #pragma unroll
            for (int qq = 0; qq < 2; qq++) {
                const int s = (row0 & 4095) + 8 * qq;
                char* dst = (char*)g_kbf +
                            ((size_t)((b * 16 + h) * 64 + (s >> 6))) * 16384;
                const int r = s & 63;
                const float2* cb  = (const float2*)&cosb[s * 32];
                const float2* sb2 = (const float2*)&sinb[s * 32];
                #pragma unroll
                for (int ni = 0; ni < 4; ni++) {
                    const int d0 = ni * 8 + tig * 2;   // 0..30, partner d0+32
                    const float k1a = acc[mi][ni][2 * qq];
                    const float k1b = acc[mi][ni][2 * qq + 1];
                    const float k2a = acc[mi][ni + 4][2 * qq];
                    const float k2b = acc[mi][ni + 4][2 * qq + 1];
                    const float2 c  = cb[d0 >> 1];
                    const float2 sn = sb2[d0 >> 1];
                    uint32_t hi, lo;
                    split2(k1a * c.x - k2a * sn.x, k1b * c.y - k2b * sn.y, hi, lo);
                    uint32_t bo = (uint32_t)(r * 128 + 2 * d0);
                    uint32_t sw = bo ^ ((bo >> 3) & 0x70);
                    *(uint32_t*)(dst + sw) = hi;
                    *(uint32_t*)(dst + 8192 + sw) = lo;
                    split2(k2a * c.x + k1a * sn.x, k2b * c.y + k1b * sn.y, hi, lo);
                    uint32_t bo2 = bo + 64;            // d0+32
                    uint32_t sw2 = bo2 ^ ((bo2 >> 3) & 0x70);
                    *(uint32_t*)(dst + sw2) = hi;
                    *(uint32_t*)(dst + 8192 + sw2) = lo;
                }
            }
        }
    } else {
        // ---- V columns: smem transpose (stage smem is free) -> g_vbf -------
        unsigned short* VH = (unsigned short*)(dyn_smem + OFF_STG);
        unsigned short* VL = VH + 128 * 136;   // 136-ushort pitch (272B = 17x16)
        #pragma unroll
        for (int mi = 0; mi < 2; mi++)
            #pragma unroll
            for (int ni = 0; ni < 8; ni++)
                #pragma unroll
                for (int q = 0; q < 4; q++) {
                    const int d = wn * 64 + ni * 8 + tig * 2 + (q & 1);
                    const int srow = wm * 32 + mi * 16 + g + 8 * (q >> 1);
                    const float v = acc[mi][ni][q];
                    const __nv_bfloat16 hb = __float2bfloat16(v);
                    const __nv_bfloat16 lb =
                        __float2bfloat16(v - __bfloat162float(hb));
                    VH[d * 136 + srow] = __bfloat16_as_ushort(hb);
                    VL[d * 136 + srow] = __bfloat16_as_ushort(lb);
                }
        __syncthreads();
        const int c = t & 127, sel = t >> 7;
        const int head = (bx - 8) * 2 + (c >> 6);
        const int dd = c & 63;
        const int b = by >> 5;
        const int scb = (by & 31) * 2;
        const unsigned short* src = (sel ? VL : VH) + c * 136;
        #pragma unroll
        for (int blk8 = 0; blk8 < 16; blk8++) {
            const uint4 v = *(const uint4*)(src + blk8 * 8);
            char* dst = (char*)g_vbf +
                        ((size_t)((b * 16 + head) * 64 + scb + (blk8 >> 3))) * 16384 +
                        sel * 8192;
            uint32_t bo = (uint32_t)(dd * 128 + 16 * (blk8 & 7));
            uint32_t sw = bo ^ ((bo >> 3) & 0x70);
            *(uint4*)(dst + sw) = v;
        }
    }
}

// -------- o GEMM: A = g_obf (attn out), epilogue -> out fp32 + bias ---------
__global__ __launch_bounds__(256) void o_mma_kernel(
    const float* __restrict__ bias, float* __restrict__ out)
{
    const uint32_t sb = smem_u32(dyn_smem);
    const int t = threadIdx.x, w = t >> 5, lane = t & 31;
    const int wm = w & 3, wn = w >> 2, g = lane >> 2, tig = lane & 3;
    const int bx = blockIdx.x, by = blockIdx.y;   // bx 0..7, by 0..15

    float acc[2][8][4];
    mma_tile_mainloop((const char*)g_obf + (size_t)by * KCH * 2 * BLK,
                      (const char*)g_Bo + (size_t)bx * KCH * 2 * BLK, KCH, sb, acc);

    #pragma unroll
    for (int mi = 0; mi < 2; mi++) {
        const int row0 = by * 128 + wm * 32 + mi * 16 + g;
        #pragma unroll
        for (int ni = 0; ni < 8; ni++) {
            const int col = bx * 128 + wn * 64 + ni * 8 + tig * 2;
            const float2 bb = *(const float2*)&bias[col];
            *(float2*)&out[(size_t)row0 * DIM + col] =
                make_float2(acc[mi][ni][0] + bb.x, acc[mi][ni][1] + bb.y);
            *(float2*)&out[(size_t)(row0 + 8) * DIM + col] =
                make_float2(acc[mi][ni][2] + bb.x, acc[mi][ni][3] + bb.y);
        }
    }
}

// -------- Flash attention, fixed-max softmax (clip guarantees max<=11) ------
#define ACH 32768      // per stage: K(hi|lo 16KB) + V(hi|lo 16KB)

__global__ __launch_bounds__(256) void attn_mma_kernel()
{
    const uint32_t sb = smem_u32(dyn_smem);
    const int t = threadIdx.x, w = t >> 5, lane = t & 31;
    const int bh = blockIdx.y;
    const int b = bh >> 4, h = bh & 15;
    const int n0 = blockIdx.x * 128;
    const int g = lane >> 2, tig = lane & 3;
    const int l15 = lane & 15;
    const uint32_t kb16 = (uint32_t)(lane & 16);
    const uint32_t mask = (uint32_t)((lane & 7) << 4);
    const uint32_t stg = sb + 64;

    if (t == 0) { mbar_init(sb, 1); mbar_init(sb + 8, 1); }
    __syncthreads();
    asm volatile("fence.proxy.async.shared::cta;" ::: "memory");

    const char* Qg = (const char*)g_qbf + (size_t)bh * 65536 + (size_t)n0 * 128;
    if (t == 0) {
        mbar_expect(sb, 32768);
        bulk_g2s(stg,         Qg,         16384, sb);
        bulk_g2s(stg + 16384, Qg + 32768, 16384, sb);
    }
    mbar_wait(sb, 0);

    uint32_t aqh[4][4], aql[4][4];
    #pragma unroll
    for (int ks = 0; ks < 4; ks++) {
        const uint32_t kx = ((uint32_t)(ks * 32) + kb16) ^ mask;
        const uint32_t ro = (uint32_t)((w * 16 + l15) * 128);
        ldmx4(aqh[ks], stg + ro + kx);
        ldmx4(aql[ks], stg + 16384 + ro + kx);
    }
    __syncthreads();

    const char* Kg = (const char*)g_kbf + (size_t)bh * 64 * 16384;
    const char* Vg = (const char*)g_vbf + (size_t)bh * 64 * 16384;
    if (t == 0) {
        #pragma unroll
        for (int c = 0; c < 2; c++) {
            mbar_expect(sb + 8 * c, 32768);
            bulk_g2s(stg + c * ACH,         Kg + (size_t)c * 16384, 16384, sb + 8 * c);
            bulk_g2s(stg + c * ACH + 16384, Vg + (size_t)c * 16384, 16384, sb + 8 * c);
        }
    }
    int ph0 = 1, ph1 = 0;

    // fixed max = 11 (logits clipped to [-11,11]): exp(s-11), plain accumulation
    float lA = 0.f, lB = 0.f;
    float o[8][4];
    #pragma unroll
    for (int ni = 0; ni < 8; ni++)
        #pragma unroll
        for (int q = 0; q < 4; q++) o[ni][q] = 0.f;

    for (int sc = 0; sc < 64; sc++) {
        const int s = sc & 1;
        if (s == 0) { mbar_wait(sb, ph0); ph0 ^= 1; }
        else        { mbar_wait(sb + 8, ph1); ph1 ^= 1; }
        const uint32_t kb = stg + s * ACH;
        const uint32_t vb = kb + 16384;

        float sacc[8][4];
        #pragma unroll
        for (int ni = 0; ni < 8; ni++)
            #pragma unroll
            for (int q = 0; q < 4; q++) sacc[ni][q] = 0.f;

        #pragma unroll
        for (int ks = 0; ks < 4; ks++) {
            const uint32_t kx = ((uint32_t)(ks * 32) + kb16) ^ mask;
            #pragma unroll
            for (int p = 0; p < 4; p++) {
                uint32_t kh[4], kl[4];
                const uint32_t ro = (uint32_t)((p * 16 + l15) * 128);
                ldmx4(kh, kb + ro + kx);
                ldmx4(kl, kb + 8192 + ro + kx);
                mma16816(sacc[2 * p + 0], aqh[ks], kh[0], kh[2]);
                mma16816(sacc[2 * p + 1], aqh[ks], kh[1], kh[3]);
                mma16816(sacc[2 * p + 0], aqh[ks], kl[0], kl[2]);
                mma16816(sacc[2 * p + 1], aqh[ks], kl[1], kl[3]);
                mma16816(sacc[2 * p + 0], aql[ks], kh[0], kh[2]);
                mma16816(sacc[2 * p + 1], aql[ks], kh[1], kh[3]);
            }
        }

        // p = exp(clip(s) - 11); accumulate row sums (no per-chunk reduction)
        #pragma unroll
        for (int ni = 0; ni < 8; ni++) {
            sacc[ni][0] = __expf(fminf(0.f, fmaxf(-22.f, sacc[ni][0] - 11.f)));
            sacc[ni][1] = __expf(fminf(0.f, fmaxf(-22.f, sacc[ni][1] - 11.f)));
            sacc[ni][2] = __expf(fminf(0.f, fmaxf(-22.f, sacc[ni][2] - 11.f)));
            sacc[ni][3] = __expf(fminf(0.f, fmaxf(-22.f, sacc[ni][3] - 11.f)));
            lA += sacc[ni][0] + sacc[ni][1];
            lB += sacc[ni][2] + sacc[ni][3];
        }

        // O += P V (3-pass; P fragments packed from sacc in A-operand order)
        #pragma unroll
        for (int ks = 0; ks < 4; ks++) {
            uint32_t pah[4], pal[4];
            split2(sacc[2 * ks][0],     sacc[2 * ks][1],     pah[0], pal[0]);
            split2(sacc[2 * ks][2],     sacc[2 * ks][3],     pah[1], pal[1]);
            split2(sacc[2 * ks + 1][0], sacc[2 * ks + 1][1], pah[2], pal[2]);
            split2(sacc[2 * ks + 1][2], sacc[2 * ks + 1][3], pah[3], pal[3]);
            const uint32_t kx = ((uint32_t)(ks * 32) + kb16) ^ mask;
            #pragma unroll
            for (int p = 0; p < 4; p++) {
                uint32_t vh[4], vl[4];
                const uint32_t ro = (uint32_t)((p * 16 + l15) * 128);
                ldmx4(vh, vb + ro + kx);
                ldmx4(vl, vb + 8192 + ro + kx);
                mma16816(o[2 * p + 0], pah, vh[0], vh[2]);
                mma16816(o[2 * p + 1], pah, vh[1], vh[3]);
                mma16816(o[2 * p + 0], pah, vl[0], vl[2]);
                mma16816(o[2 * p + 1], pah, vl[1], vl[3]);
                mma16816(o[2 * p + 0], pal, vh[0], vh[2]);
                mma16816(o[2 * p + 1], pal, vh[1], vh[3]);
            }
        }
        __syncthreads();
        if (t == 0 && sc + 2 < 64) {
            const int nc = sc + 2;
            const uint32_t dst = stg + s * ACH;
            mbar_expect(sb + 8 * s, 32768);
            bulk_g2s(dst,         Kg + (size_t)nc * 16384, 16384, sb + 8 * s);
            bulk_g2s(dst + 16384, Vg + (size_t)nc * 16384, 16384, sb + 8 * s);
        }
    }

    // finalize: quad-reduce row sums, normalize, write split-bf16 to g_obf
    lA += __shfl_xor_sync(0xffffffffu, lA, 1);
    lA += __shfl_xor_sync(0xffffffffu, lA, 2);
    lB += __shfl_xor_sync(0xffffffffu, lB, 1);
    lB += __shfl_xor_sync(0xffffffffu, lB, 2);
    const float iA = 1.f / lA, iB = 1.f / lB;
    const int growA = b * NLAT + n0 + w * 16 + g;
    const int mt = growA >> 7;
    char* ob = (char*)g_obf + ((size_t)(mt * KCH + h) * 2) * BLK;
    const int rA = growA & 127;
    #pragma unroll
    for (int ni = 0; ni < 8; ni++) {
        uint32_t hi, lo;
        split2(o[ni][0] * iA, o[ni][1] * iA, hi, lo);
        uint32_t bo = (uint32_t)(rA * 128 + 16 * ni + 4 * tig);
        uint32_t sw = bo ^ ((bo >> 3) & 0x70);
        *(uint32_t*)(ob + sw) = hi;
        *(uint32_t*)(ob + BLK + sw) = lo;
        split2(o[ni][2] * iB, o[ni][3] * iB, hi, lo);
        uint32_t bo2 = (uint32_t)((rA + 8) * 128 + 16 * ni + 4 * tig);
        uint32_t sw2 = bo2 ^ ((bo2 >> 3) & 0x70);
        *(uint32_t*)(ob + sw2) = hi;
        *(uint32_t*)(ob + BLK + sw2) = lo;
    }
}

// ---------------- host launcher --------------------------------------------
extern "C" void kernel_launch(void* const* d_in, const int* in_sizes, int n_in,
                              void* d_out, int out_size)
{
    const float* latents  = (const float*)d_in[0];
    const float* context  = (const float*)d_in[1];
    const float* cosb     = (const float*)d_in[2];
    const float* sinb     = (const float*)d_in[3];
    const float* ln_lat_g = (const float*)d_in[4];
    const float* ln_lat_b = (const float*)d_in[5];
    const float* ln_ctx_g = (const float*)d_in[6];
    const float* ln_ctx_b = (const float*)d_in[7];
    const float* Wq       = (const float*)d_in[8];
    const float* Wkv      = (const float*)d_in[9];
    const float* Wo       = (const float*)d_in[10];
    const float* bo       = (const float*)d_in[11];
    float* out = (float*)d_out;

    uint4 *pAq, *pA;
    cudaGetSymbolAddress((void**)&pAq, g_Aq);
    cudaGetSymbolAddress((void**)&pA,  g_A);

    const int gemm_smem = OFF_STG + NSTG * STG_BYTES;   // 197632
    cudaFuncSetAttribute(kvq_mma_kernel, cudaFuncAttributeMaxDynamicSharedMemorySize, gemm_smem);
    cudaFuncSetAttribute(o_mma_kernel,   cudaFuncAttributeMaxDynamicSharedMemorySize, gemm_smem);
    const int at_smem_bytes = 64 + 2 * ACH;   // 65600
    cudaFuncSetAttribute(attn_mma_kernel, cudaFuncAttributeMaxDynamicSharedMemorySize, at_smem_bytes);

    // launch 0: ctx LayerNorm + A-prep
    ln_prep_kernel<<<(BATCH * SEQ) / 8, 256>>>(context, ln_ctx_g, ln_ctx_b, pA);
    // launch 1: all weight preps
    wprep_all_kernel<<<dim3(KCH, 32), 256>>>(Wq, Wkv, Wo);
    // launch 2: latent LayerNorm + A-prep
    ln_prep_kernel<<<(BATCH * NLAT) / 8, 256>>>(latents, ln_lat_g, ln_lat_b, pAq);
    // launch 3 (ncu-captured): fused kv + q projections
    kvq_mma_kernel<<<dim3(NT, 272), 256, gemm_smem>>>(cosb, sinb);
    // launch 4: attention -> g_obf
    attn_mma_kernel<<<dim3(NLAT / 128, BH), 256, at_smem_bytes>>>();
    // launch 5: output projection + bias
    o_mma_kernel<<<dim3(8, 16), 256, gemm_smem>>>(bo, out);
}

// round 16
// speedup vs baseline: 1.0114x; 1.0114x over previous
#include <cuda_runtime.h>
#include <cuda_bf16.h>
#include <math.h>
#include <stdint.h>

#define BATCH 8
#define NLAT  256
#define SEQ   4096
#define DIM   1024
#define HEADS 16
#define DHEAD 64
#define INNER 1024
#define EPSLN 1e-5f
#define BH    (BATCH * HEADS)     // 128

// ---- GEMM geometry
#define GM     (BATCH * SEQ)      // 32768
#define GN     (2 * INNER)        // 2048
#define MT     (GM / 128)         // 256 m tiles (kv)
#define NT     (GN / 128)         // 16 n tiles (kv)
#define KCH    (DIM / 64)         // 16 k chunks of 64
#define BLK    16384              // one 128row x 128B swizzled block
#define NSTG   3
#define STG_BYTES (4 * BLK)       // Ah|Al|Bh|Bl = 64KB per stage
#define OFF_STG  1024

// ---------------- scratch (device globals: no runtime allocation) ----------
__device__ uint4 g_A[(size_t)MT * KCH * 2 * BLK / 16];        // 134 MB ctx split-bf16
__device__ uint4 g_B[(size_t)NT * KCH * 2 * BLK / 16];        //   8 MB Wkv split
__device__ uint4 g_Aq[(size_t)16 * KCH * 2 * BLK / 16];       //   8 MB lat split
__device__ uint4 g_Bq[(size_t)8 * KCH * 2 * BLK / 16];        //   4 MB Wq split
__device__ uint4 g_Bo[(size_t)8 * KCH * 2 * BLK / 16];        //   4 MB Wo split
__device__ uint4 g_obf[(size_t)16 * KCH * 2 * BLK / 16];      //   8 MB attn-out split
__device__ uint4 g_qbf[(size_t)BH * 2 * 256 * 128 / 16];      //   8 MB Q hi/lo swizzled
__device__ uint4 g_kbf[(size_t)BH * 64 * 16384 / 16];         // 128 MB K hi/lo (roped)
__device__ uint4 g_vbf[(size_t)BH * 64 * 16384 / 16];         // 128 MB V^T hi/lo

// ---------------- PTX helpers ----------------------------------------------
__device__ __forceinline__ uint32_t smem_u32(const void* p) {
    uint32_t a;
    asm("{ .reg .u64 t; cvta.to.shared.u64 t, %1; cvt.u32.u64 %0, t; }"
        : "=r"(a) : "l"(p));
    return a;
}
__device__ __forceinline__ void mbar_init(uint32_t m, uint32_t cnt) {
    asm volatile("mbarrier.init.shared.b64 [%0], %1;" :: "r"(m), "r"(cnt) : "memory");
}
__device__ __forceinline__ void mbar_expect(uint32_t m, uint32_t bytes) {
    asm volatile("mbarrier.arrive.expect_tx.shared.b64 _, [%0], %1;"
                 :: "r"(m), "r"(bytes) : "memory");
}
__device__ __forceinline__ void mbar_wait(uint32_t m, int ph) {
    asm volatile(
        "{\n\t.reg .pred P;\n\t"
        "W%=:\n\t"
        "mbarrier.try_wait.parity.shared.b64 P, [%0], %1;\n\t"
        "@!P bra W%=;\n\t}"
        :: "r"(m), "r"(ph) : "memory");
}
__device__ __forceinline__ void bulk_g2s(uint32_t dst, const void* src,
                                         uint32_t bytes, uint32_t mbar) {
    asm volatile(
        "cp.async.bulk.shared::cluster.global.mbarrier::complete_tx::bytes "
        "[%0], [%1], %2, [%3];"
        :: "r"(dst), "l"(src), "r"(bytes), "r"(mbar) : "memory");
}
__device__ __forceinline__ void ldmx4(uint32_t* r, uint32_t addr) {
    asm volatile("ldmatrix.sync.aligned.m8n8.x4.shared.b16 {%0,%1,%2,%3}, [%4];"
                 : "=r"(r[0]), "=r"(r[1]), "=r"(r[2]), "=r"(r[3]) : "r"(addr));
}
__device__ __forceinline__ void mma16816(float* c, const uint32_t* a,
                                         uint32_t b0, uint32_t b1) {
    asm volatile(
        "mma.sync.aligned.m16n8k16.row.col.f32.bf16.bf16.f32 "
        "{%0,%1,%2,%3}, {%4,%5,%6,%7}, {%8,%9}, {%0,%1,%2,%3};"
        : "+f"(c[0]), "+f"(c[1]), "+f"(c[2]), "+f"(c[3])
        : "r"(a[0]), "r"(a[1]), "r"(a[2]), "r"(a[3]), "r"(b0), "r"(b1));
}
__device__ __forceinline__ void split2(float a, float b, uint32_t& hi, uint32_t& lo) {
    __nv_bfloat16 ha = __float2bfloat16(a), hb = __float2bfloat16(b);
    float ra = a - __bfloat162float(ha), rb = b - __bfloat162float(hb);
    __nv_bfloat16 la = __float2bfloat16(ra), lb = __float2bfloat16(rb);
    hi = (uint32_t)__bfloat16_as_ushort(ha) | ((uint32_t)__bfloat16_as_ushort(hb) << 16);
    lo = (uint32_t)__bfloat16_as_ushort(la) | ((uint32_t)__bfloat16_as_ushort(lb) << 16);
}

// ---------------- shared split-bf16 mma mainloop ----------------------------
// Pass-major inner loop: each of the 16 accumulator pairs is touched once per
// pass, giving 15 independent mma between RAW revisits of any accumulator.
extern __shared__ char dyn_smem[];

__device__ __forceinline__ void mma_tile_mainloop(
    const char* __restrict__ Ab, const char* __restrict__ Bb, const int kch,
    const uint32_t sb, float (&acc)[2][8][4])
{
    const int t = threadIdx.x;
    const int w = t >> 5, lane = t & 31;
    const int wm = w & 3, wn = w >> 2;          // 4 x 2 warp grid

    if (t == 0) {
        #pragma unroll
        for (int i = 0; i < NSTG; i++) mbar_init(sb + 8 * i, 1);
    }
    __syncthreads();
    asm volatile("fence.proxy.async.shared::cta;" ::: "memory");

    if (t == 0) {
        #pragma unroll
        for (int c = 0; c < NSTG; c++) {
            uint32_t st = sb + OFF_STG + c * STG_BYTES;
            mbar_expect(sb + 8 * c, STG_BYTES);
            bulk_g2s(st,           Ab + (size_t)c * 2 * BLK, 2 * BLK, sb + 8 * c);
            bulk_g2s(st + 2 * BLK, Bb + (size_t)c * 2 * BLK, 2 * BLK, sb + 8 * c);
        }
    }

    const int l15 = lane & 15;
    const uint32_t kb16 = (uint32_t)(lane & 16);
    const uint32_t mask = (uint32_t)((lane & 7) << 4);
    uint32_t aoff[2], boff[4];
    #pragma unroll
    for (int mi = 0; mi < 2; mi++) aoff[mi] = (uint32_t)((wm * 32 + mi * 16 + l15) * 128);
    #pragma unroll
    for (int p = 0; p < 4; p++)    boff[p]  = (uint32_t)((wn * 64 + p * 16 + l15) * 128);

    #pragma unroll
    for (int mi = 0; mi < 2; mi++)
        #pragma unroll
        for (int ni = 0; ni < 8; ni++)
            #pragma unroll
            for (int q = 0; q < 4; q++) acc[mi][ni][q] = 0.f;

    int ph[NSTG] = {0, 0, 0};

    for (int kc = 0; kc < kch; kc++) {
        const int s = kc % NSTG;
        mbar_wait(sb + 8 * s, ph[s]); ph[s] ^= 1;
        const uint32_t base = sb + OFF_STG + s * STG_BYTES;

        #pragma unroll
        for (int ks = 0; ks < 4; ks++) {
            const uint32_t kx = ((uint32_t)(ks * 32) + kb16) ^ mask;
            uint32_t ah[2][4], al[2][4], bh[4][4], bl[4][4];
            #pragma unroll
            for (int mi = 0; mi < 2; mi++) {
                ldmx4(ah[mi], base + aoff[mi] + kx);
                ldmx4(al[mi], base + BLK + aoff[mi] + kx);
            }
            #pragma unroll
            for (int p = 0; p < 4; p++) {
                ldmx4(bh[p], base + 2 * BLK + boff[p] + kx);
                ldmx4(bl[p], base + 3 * BLK + boff[p] + kx);
            }
            // pass 1: Ah * Bh  (16 independent accumulator updates)
            #pragma unroll
            for (int mi = 0; mi < 2; mi++)
                #pragma unroll
                for (int p = 0; p < 4; p++) {
                    mma16816(acc[mi][2 * p + 0], ah[mi], bh[p][0], bh[p][2]);
                    mma16816(acc[mi][2 * p + 1], ah[mi], bh[p][1], bh[p][3]);
                }
            // pass 2: Ah * Bl
            #pragma unroll
            for (int mi = 0; mi < 2; mi++)
                #pragma unroll
                for (int p = 0; p < 4; p++) {
                    mma16816(acc[mi][2 * p + 0], ah[mi], bl[p][0], bl[p][2]);
                    mma16816(acc[mi][2 * p + 1], ah[mi], bl[p][1], bl[p][3]);
                }
            // pass 3: Al * Bh
            #pragma unroll
            for (int mi = 0; mi < 2; mi++)
                #pragma unroll
                for (int p = 0; p < 4; p++) {
                    mma16816(acc[mi][2 * p + 0], al[mi], bh[p][0], bh[p][2]);
                    mma16816(acc[mi][2 * p + 1], al[mi], bh[p][1], bh[p][3]);
                }
        }
        __syncthreads();
        const int nxt = kc + NSTG;
        if (t == 0 && nxt < kch) {
            mbar_expect(sb + 8 * s, STG_BYTES);
            bulk_g2s(base,           Ab + (size_t)nxt * 2 * BLK, 2 * BLK, sb + 8 * s);
            bulk_g2s(base + 2 * BLK, Bb + (size_t)nxt * 2 * BLK, 2 * BLK, sb + 8 * s);
        }
    }
}

// -------- LayerNorm (warp-per-row) fused with split-bf16 A-prep -------------
__global__ __launch_bounds__(256) void ln_prep_kernel(
    const float* __restrict__ x, const float* __restrict__ gam,
    const float* __restrict__ bet, uint4* __restrict__ dstb)
{
    const int wid = threadIdx.x >> 5, lane = threadIdx.x & 31;
    const int row = blockIdx.x * 8 + wid;
    const float4* xr = (const float4*)(x + (size_t)row * DIM);

    float4 v[8];
    float s = 0.f;
    #pragma unroll
    for (int i = 0; i < 8; i++) {
        v[i] = xr[i * 32 + lane];
        s += v[i].x + v[i].y + v[i].z + v[i].w;
    }
    #pragma unroll
    for (int off = 16; off; off >>= 1) s += __shfl_xor_sync(0xffffffffu, s, off);
    const float mu = s * (1.0f / DIM);

    float s2 = 0.f;
    #pragma unroll
    for (int i = 0; i < 8; i++) {
        v[i].x -= mu; v[i].y -= mu; v[i].z -= mu; v[i].w -= mu;
        s2 += v[i].x * v[i].x + v[i].y * v[i].y + v[i].z * v[i].z + v[i].w * v[i].w;
    }
    #pragma unroll
    for (int off = 16; off; off >>= 1) s2 += __shfl_xor_sync(0xffffffffu, s2, off);
    const float rs = rsqrtf(s2 * (1.0f / DIM) + EPSLN);

    const int mt = row >> 7, r = row & 127;
    char* dst0 = (char*)dstb + (size_t)(mt * KCH) * 2 * BLK;
    #pragma unroll
    for (int i = 0; i < 8; i++) {
        const int slot = i * 32 + lane;          // float4 slot 0..255
        const float4 gg = ((const float4*)gam)[slot];
        const float4 bb = ((const float4*)bet)[slot];
        const float o0 = v[i].x * rs * gg.x + bb.x;
        const float o1 = v[i].y * rs * gg.y + bb.y;
        const float o2 = v[i].z * rs * gg.z + bb.z;
        const float o3 = v[i].w * rs * gg.w + bb.w;
        uint32_t h0, l0, h1, l1;
        split2(o0, o1, h0, l0);
        split2(o2, o3, h1, l1);
        const int chunk = slot >> 4;
        const int c = (slot & 15) * 4;
        uint32_t bo = (uint32_t)(r * 128 + c * 2);
        uint32_t sw = bo ^ ((bo >> 3) & 0x70);
        char* dst = dst0 + (size_t)chunk * 2 * BLK + sw;
        *(uint2*)dst = make_uint2(h0, h1);
        *(uint2*)(dst + BLK) = make_uint2(l0, l1);
    }
}

// -------- all 3 weight preps in one launch: grid (KCH, 32) ------------------
__global__ __launch_bounds__(256) void wprep_all_kernel(
    const float* __restrict__ Wq, const float* __restrict__ Wkv,
    const float* __restrict__ Wo)
{
    __shared__ float ws[64][132];     // 132-float pitch: 528B = 33x16, aligned
    const int by = blockIdx.y;
    const float* W;
    uint4* dstb;
    int N, nt;
    if (by < 8)       { W = Wq;  dstb = g_Bq; N = INNER; nt = by; }
    else if (by < 24) { W = Wkv; dstb = g_B;  N = GN;    nt = by - 8; }
    else              { W = Wo;  dstb = g_Bo; N = DIM;   nt = by - 24; }

    const int chunk = blockIdx.x;     // 0..15 (64 k-values each)
    const int t = threadIdx.x;
    {
        const int rr = t >> 5;        // 0..7
        const int cc = (t & 31) * 4;
        #pragma unroll
        for (int i = 0; i < 8; i++) {
            const int k = chunk * 64 + rr + i * 8;
            *(float4*)&ws[rr + i * 8][cc] =
                *(const float4*)&W[(size_t)k * N + nt * 128 + cc];
        }
    }
    __syncthreads();
    const int n = t & 127, sel = t >> 7;
    char* dst = (char*)dstb + ((size_t)(nt * KCH + chunk) * 2) * BLK + sel * BLK;
    #pragma unroll
    for (int j = 0; j < 8; j++) {
        uint32_t outv[4];
        #pragma unroll
        for (int kk = 0; kk < 4; kk++) {
            const int k2 = j * 8 + kk * 2;
            uint32_t hi, lo;
            split2(ws[k2][n], ws[k2 + 1][n], hi, lo);
            outv[kk] = sel ? lo : hi;
        }
        uint32_t bo = (uint32_t)(n * 128 + 16 * j);
        uint32_t sw = bo ^ ((bo >> 3) & 0x70);
        *(uint4*)(dst + sw) = make_uint4(outv[0], outv[1], outv[2], outv[3]);
    }
}

// -------- kv GEMM: fused epilogue -> g_kbf (RoPE) / g_vbf (transpose) -------
__global__ __launch_bounds__(256) void kv_mma_kernel(
    const float* __restrict__ cosb, const float* __restrict__ sinb)
{
    const uint32_t sb = smem_u32(dyn_smem);
    const int t = threadIdx.x, w = t >> 5, lane = t & 31;
    const int wm = w & 3, wn = w >> 2, g = lane >> 2, tig = lane & 3;
    const int bx = blockIdx.x, by = blockIdx.y;

    float acc[2][8][4];
    mma_tile_mainloop((const char*)g_A + (size_t)by * KCH * 2 * BLK,
                      (const char*)g_B + (size_t)bx * KCH * 2 * BLK, KCH, sb, acc);

    if (bx < 8) {
        // ---- K columns: RoPE in registers, write g_kbf swizzled hi/lo ----
        const int h = bx * 2 + wn;
        #pragma unroll
        for (int mi = 0; mi < 2; mi++) {
            const int row0 = by * 128 + wm * 32 + mi * 16 + g;
            const int b = row0 >> 12;
            #pragma unroll
            for (int qq = 0; qq < 2; qq++) {
                const int s = (row0 & 4095) + 8 * qq;
                char* dst = (char*)g_kbf +
                            ((size_t)((b * 16 + h) * 64 + (s >> 6))) * 16384;
                const int r = s & 63;
                const float2* cb  = (const float2*)&cosb[s * 32];
                const float2* sb2 = (const float2*)&sinb[s * 32];
                #pragma unroll
                for (int ni = 0; ni < 4; ni++) {
                    const int d0 = ni * 8 + tig * 2;   // 0..30, partner d0+32
                    const float k1a = acc[mi][ni][2 * qq];
                    const float k1b = acc[mi][ni][2 * qq + 1];
                    const float k2a = acc[mi][ni + 4][2 * qq];
                    const float k2b = acc[mi][ni + 4][2 * qq + 1];
                    const float2 c  = cb[d0 >> 1];
                    const float2 sn = sb2[d0 >> 1];
                    uint32_t hi, lo;
                    split2(k1a * c.x - k2a * sn.x, k1b * c.y - k2b * sn.y, hi, lo);
                    uint32_t bo = (uint32_t)(r * 128 + 2 * d0);
                    uint32_t sw = bo ^ ((bo >> 3) & 0x70);
                    *(uint32_t*)(dst + sw) = hi;
                    *(uint32_t*)(dst + 8192 + sw) = lo;
                    split2(k2a * c.x + k1a * sn.x, k2b * c.y + k1b * sn.y, hi, lo);
                    uint32_t bo2 = bo + 64;            // d0+32
                    uint32_t sw2 = bo2 ^ ((bo2 >> 3) & 0x70);
                    *(uint32_t*)(dst + sw2) = hi;
                    *(uint32_t*)(dst + 8192 + sw2) = lo;
                }
            }
        }
    } else {
        // ---- V columns: smem transpose (stage smem is free) -> g_vbf -------
        unsigned short* VH = (unsigned short*)(dyn_smem + OFF_STG);
        unsigned short* VL = VH + 128 * 136;   // 136-ushort pitch (272B = 17x16)
        #pragma unroll
        for (int mi = 0; mi < 2; mi++)
            #pragma unroll
            for (int ni = 0; ni < 8; ni++)
                #pragma unroll
                for (int q = 0; q < 4; q++) {
                    const int d = wn * 64 + ni * 8 + tig * 2 + (q & 1);
                    const int srow = wm * 32 + mi * 16 + g + 8 * (q >> 1);
                    const float v = acc[mi][ni][q];
                    const __nv_bfloat16 hb = __float2bfloat16(v);
                    const __nv_bfloat16 lb =
                        __float2bfloat16(v - __bfloat162float(hb));
                    VH[d * 136 + srow] = __bfloat16_as_ushort(hb);
                    VL[d * 136 + srow] = __bfloat16_as_ushort(lb);
                }
        __syncthreads();
        const int c = t & 127, sel = t >> 7;
        const int head = (bx - 8) * 2 + (c >> 6);
        const int dd = c & 63;
        const int b = by >> 5;
        const int scb = (by & 31) * 2;
        const unsigned short* src = (sel ? VL : VH) + c * 136;
        #pragma unroll
        for (int blk8 = 0; blk8 < 16; blk8++) {
            const uint4 v = *(const uint4*)(src + blk8 * 8);
            char* dst = (char*)g_vbf +
                        ((size_t)((b * 16 + head) * 64 + scb + (blk8 >> 3))) * 16384 +
                        sel * 8192;
            uint32_t bo = (uint32_t)(dd * 128 + 16 * (blk8 & 7));
            uint32_t sw = bo ^ ((bo >> 3) & 0x70);
            *(uint4*)(dst + sw) = v;
        }
    }
}

// -------- q GEMM: epilogue (x0.125 folded) -> g_qbf -------------------------
__global__ __launch_bounds__(256) void q_mma_kernel()
{
    const uint32_t sb = smem_u32(dyn_smem);
    const int t = threadIdx.x, w = t >> 5, lane = t & 31;
    const int wm = w & 3, wn = w >> 2, g = lane >> 2, tig = lane & 3;
    const int bx = blockIdx.x, by = blockIdx.y;   // bx 0..7, by 0..15

    float acc[2][8][4];
    mma_tile_mainloop((const char*)g_Aq + (size_t)by * KCH * 2 * BLK,
                      (const char*)g_Bq + (size_t)bx * KCH * 2 * BLK, KCH, sb, acc);

    const int h = bx * 2 + wn;
    #pragma unroll
    for (int mi = 0; mi < 2; mi++) {
        const int grow = by * 128 + wm * 32 + mi * 16 + g;
        const int b = grow >> 8, n = grow & 255;
        char* base = (char*)g_qbf + (size_t)(b * 16 + h) * 65536;
        #pragma unroll
        for (int ni = 0; ni < 8; ni++) {
            uint32_t hi, lo;
            split2(acc[mi][ni][0] * 0.125f, acc[mi][ni][1] * 0.125f, hi, lo);
            uint32_t bo = (uint32_t)(n * 128 + 16 * ni + 4 * tig);
            uint32_t sw = bo ^ ((bo >> 3) & 0x70);
            *(uint32_t*)(base + sw) = hi;
            *(uint32_t*)(base + 32768 + sw) = lo;
            split2(acc[mi][ni][2] * 0.125f, acc[mi][ni][3] * 0.125f, hi, lo);
            uint32_t bo2 = (uint32_t)((n + 8) * 128 + 16 * ni + 4 * tig);
            uint32_t sw2 = bo2 ^ ((bo2 >> 3) & 0x70);
            *(uint32_t*)(base + sw2) = hi;
            *(uint32_t*)(base + 32768 + sw2) = lo;
        }
    }
}

// -------- o GEMM: A = g_obf (attn out), epilogue -> out fp32 + bias ---------
__global__ __launch_bounds__(256) void o_mma_kernel(
    const float* __restrict__ bias, float* __restrict__ out)
{
    const uint32_t sb = smem_u32(dyn_smem);
    const int t = threadIdx.x, w = t >> 5, lane = t & 31;
    const int wm = w & 3, wn = w >> 2, g = lane >> 2, tig = lane & 3;
    const int bx = blockIdx.x, by = blockIdx.y;   // bx 0..7, by 0..15

    float acc[2][8][4];
    mma_tile_mainloop((const char*)g_obf + (size_t)by * KCH * 2 * BLK,
                      (const char*)g_Bo + (size_t)bx * KCH * 2 * BLK, KCH, sb, acc);

    #pragma unroll
    for (int mi = 0; mi < 2; mi++) {
        const int row0 = by * 128 + wm * 32 + mi * 16 + g;
        #pragma unroll
        for (int ni = 0; ni < 8; ni++) {
            const int col = bx * 128 + wn * 64 + ni * 8 + tig * 2;
            const float2 bb = *(const float2*)&bias[col];
            *(float2*)&out[(size_t)row0 * DIM + col] =
                make_float2(acc[mi][ni][0] + bb.x, acc[mi][ni][1] + bb.y);
            *(float2*)&out[(size_t)(row0 + 8) * DIM + col] =
                make_float2(acc[mi][ni][2] + bb.x, acc[mi][ni][3] + bb.y);
        }
    }
}

// -------- Flash attention, fixed-max softmax (clip guarantees max<=11) ------
#define ACH 32768      // per stage: K(hi|lo 16KB) + V(hi|lo 16KB)

__global__ __launch_bounds__(256) void attn_mma_kernel()
{
    const uint32_t sb = smem_u32(dyn_smem);
    const int t = threadIdx.x, w = t >> 5, lane = t & 31;
    const int bh = blockIdx.y;
    const int b = bh >> 4, h = bh & 15;
    const int n0 = blockIdx.x * 128;
    const int g = lane >> 2, tig = lane & 3;
    const int l15 = lane & 15;
    const uint32_t kb16 = (uint32_t)(lane & 16);
    const uint32_t mask = (uint32_t)((lane & 7) << 4);
    const uint32_t stg = sb + 64;

    if (t == 0) { mbar_init(sb, 1); mbar_init(sb + 8, 1); }
    __syncthreads();
    asm volatile("fence.proxy.async.shared::cta;" ::: "memory");

    const char* Qg = (const char*)g_qbf + (size_t)bh * 65536 + (size_t)n0 * 128;
    if (t == 0) {
        mbar_expect(sb, 32768);
        bulk_g2s(stg,         Qg,         16384, sb);
        bulk_g2s(stg + 16384, Qg + 32768, 16384, sb);
    }
    mbar_wait(sb, 0);

    uint32_t aqh[4][4], aql[4][4];
    #pragma unroll
    for (int ks = 0; ks < 4; ks++) {
        const uint32_t kx = ((uint32_t)(ks * 32) + kb16) ^ mask;
        const uint32_t ro = (uint32_t)((w * 16 + l15) * 128);
        ldmx4(aqh[ks], stg + ro + kx);
        ldmx4(aql[ks], stg + 16384 + ro + kx);
    }
    __syncthreads();

    const char* Kg = (const char*)g_kbf + (size_t)bh * 64 * 16384;
    const char* Vg = (const char*)g_vbf + (size_t)bh * 64 * 16384;
    if (t == 0) {
        #pragma unroll
        for (int c = 0; c < 2; c++) {
            mbar_expect(sb + 8 * c, 32768);
            bulk_g2s(stg + c * ACH,         Kg + (size_t)c * 16384, 16384, sb + 8 * c);
            bulk_g2s(stg + c * ACH + 16384, Vg + (size_t)c * 16384, 16384, sb + 8 * c);
        }
    }
    int ph0 = 1, ph1 = 0;

    // fixed max = 11 (logits clipped to [-11,11]): exp(s-11), plain accumulation
    float lA = 0.f, lB = 0.f;
    float o[8][4];
    #pragma unroll
    for (int ni = 0; ni < 8; ni++)
        #pragma unroll
        for (int q = 0; q < 4; q++) o[ni][q] = 0.f;

    for (int sc = 0; sc < 64; sc++) {
        const int s = sc & 1;
        if (s == 0) { mbar_wait(sb, ph0); ph0 ^= 1; }
        else        { mbar_wait(sb + 8, ph1); ph1 ^= 1; }
        const uint32_t kb = stg + s * ACH;
        const uint32_t vb = kb + 16384;

        float sacc[8][4];
        #pragma unroll
        for (int ni = 0; ni < 8; ni++)
            #pragma unroll
            for (int q = 0; q < 4; q++) sacc[ni][q] = 0.f;

        #pragma unroll
        for (int ks = 0; ks < 4; ks++) {
            const uint32_t kx = ((uint32_t)(ks * 32) + kb16) ^ mask;
            #pragma unroll
            for (int p = 0; p < 4; p++) {
                uint32_t kh[4], kl[4];
                const uint32_t ro = (uint32_t)((p * 16 + l15) * 128);
                ldmx4(kh, kb + ro + kx);
                ldmx4(kl, kb + 8192 + ro + kx);
                mma16816(sacc[2 * p + 0], aqh[ks], kh[0], kh[2]);
                mma16816(sacc[2 * p + 1], aqh[ks], kh[1], kh[3]);
                mma16816(sacc[2 * p + 0], aqh[ks], kl[0], kl[2]);
                mma16816(sacc[2 * p + 1], aqh[ks], kl[1], kl[3]);
                mma16816(sacc[2 * p + 0], aql[ks], kh[0], kh[2]);
                mma16816(sacc[2 * p + 1], aql[ks], kh[1], kh[3]);
            }
        }

        // p = exp(clip(s) - 11); accumulate row sums (no per-chunk reduction)
        #pragma unroll
        for (int ni = 0; ni < 8; ni++) {
            sacc[ni][0] = __expf(fminf(0.f, fmaxf(-22.f, sacc[ni][0] - 11.f)));
            sacc[ni][1] = __expf(fminf(0.f, fmaxf(-22.f, sacc[ni][1] - 11.f)));
            sacc[ni][2] = __expf(fminf(0.f, fmaxf(-22.f, sacc[ni][2] - 11.f)));
            sacc[ni][3] = __expf(fminf(0.f, fmaxf(-22.f, sacc[ni][3] - 11.f)));
            lA += sacc[ni][0] + sacc[ni][1];
            lB += sacc[ni][2] + sacc[ni][3];
        }

        // O += P V (3-pass; P fragments packed from sacc in A-operand order)
        #pragma unroll
        for (int ks = 0; ks < 4; ks++) {
            uint32_t pah[4], pal[4];
            split2(sacc[2 * ks][0],     sacc[2 * ks][1],     pah[0], pal[0]);
            split2(sacc[2 * ks][2],     sacc[2 * ks][3],     pah[1], pal[1]);
            split2(sacc[2 * ks + 1][0], sacc[2 * ks + 1][1], pah[2], pal[2]);
            split2(sacc[2 * ks + 1][2], sacc[2 * ks + 1][3], pah[3], pal[3]);
            const uint32_t kx = ((uint32_t)(ks * 32) + kb16) ^ mask;
            #pragma unroll
            for (int p = 0; p < 4; p++) {
                uint32_t vh[4], vl[4];
                const uint32_t ro = (uint32_t)((p * 16 + l15) * 128);
                ldmx4(vh, vb + ro + kx);
                ldmx4(vl, vb + 8192 + ro + kx);
                mma16816(o[2 * p + 0], pah, vh[0], vh[2]);
                mma16816(o[2 * p + 1], pah, vh[1], vh[3]);
                mma16816(o[2 * p + 0], pah, vl[0], vl[2]);
                mma16816(o[2 * p + 1], pah, vl[1], vl[3]);
                mma16816(o[2 * p + 0], pal, vh[0], vh[2]);
                mma16816(o[2 * p + 1], pal, vh[1], vh[3]);
            }
        }
        __syncthreads();
        if (t == 0 && sc + 2 < 64) {
            const int nc = sc + 2;
            const uint32_t dst = stg + s * ACH;
            mbar_expect(sb + 8 * s, 32768);
            bulk_g2s(dst,         Kg + (size_t)nc * 16384, 16384, sb + 8 * s);
            bulk_g2s(dst + 16384, Vg + (size_t)nc * 16384, 16384, sb + 8 * s);
        }
    }

    // finalize: quad-reduce row sums, normalize, write split-bf16 to g_obf
    lA += __shfl_xor_sync(0xffffffffu, lA, 1);
    lA += __shfl_xor_sync(0xffffffffu, lA, 2);
    lB += __shfl_xor_sync(0xffffffffu, lB, 1);
    lB += __shfl_xor_sync(0xffffffffu, lB, 2);
    const float iA = 1.f / lA, iB = 1.f / lB;
    const int growA = b * NLAT + n0 + w * 16 + g;
    const int mt = growA >> 7;
    char* ob = (char*)g_obf + ((size_t)(mt * KCH + h) * 2) * BLK;
    const int rA = growA & 127;
    #pragma unroll
    for (int ni = 0; ni < 8; ni++) {
        uint32_t hi, lo;
        split2(o[ni][0] * iA, o[ni][1] * iA, hi, lo);
        uint32_t bo = (uint32_t)(rA * 128 + 16 * ni + 4 * tig);
        uint32_t sw = bo ^ ((bo >> 3) & 0x70);
        *(uint32_t*)(ob + sw) = hi;
        *(uint32_t*)(ob + BLK + sw) = lo;
        split2(o[ni][2] * iB, o[ni][3] * iB, hi, lo);
        uint32_t bo2 = (uint32_t)((rA + 8) * 128 + 16 * ni + 4 * tig);
        uint32_t sw2 = bo2 ^ ((bo2 >> 3) & 0x70);
        *(uint32_t*)(ob + sw2) = hi;
        *(uint32_t*)(ob + BLK + sw2) = lo;
    }
}

// ---------------- host launcher --------------------------------------------
extern "C" void kernel_launch(void* const* d_in, const int* in_sizes, int n_in,
                              void* d_out, int out_size)
{
    const float* latents  = (const float*)d_in[0];
    const float* context  = (const float*)d_in[1];
    const float* cosb     = (const float*)d_in[2];
    const float* sinb     = (const float*)d_in[3];
    const float* ln_lat_g = (const float*)d_in[4];
    const float* ln_lat_b = (const float*)d_in[5];
    const float* ln_ctx_g = (const float*)d_in[6];
    const float* ln_ctx_b = (const float*)d_in[7];
    const float* Wq       = (const float*)d_in[8];
    const float* Wkv      = (const float*)d_in[9];
    const float* Wo       = (const float*)d_in[10];
    const float* bo       = (const float*)d_in[11];
    float* out = (float*)d_out;

    uint4 *pAq, *pA;
    cudaGetSymbolAddress((void**)&pAq, g_Aq);
    cudaGetSymbolAddress((void**)&pA,  g_A);

    const int gemm_smem = OFF_STG + NSTG * STG_BYTES;   // 197632
    cudaFuncSetAttribute(kv_mma_kernel, cudaFuncAttributeMaxDynamicSharedMemorySize, gemm_smem);
    cudaFuncSetAttribute(q_mma_kernel,  cudaFuncAttributeMaxDynamicSharedMemorySize, gemm_smem);
    cudaFuncSetAttribute(o_mma_kernel,  cudaFuncAttributeMaxDynamicSharedMemorySize, gemm_smem);
    const int at_smem_bytes = 64 + 2 * ACH;   // 65600
    cudaFuncSetAttribute(attn_mma_kernel, cudaFuncAttributeMaxDynamicSharedMemorySize, at_smem_bytes);

    // launch 0: ctx LayerNorm + A-prep
    ln_prep_kernel<<<(BATCH * SEQ) / 8, 256>>>(context, ln_ctx_g, ln_ctx_b, pA);
    // launch 1: all weight preps
    wprep_all_kernel<<<dim3(KCH, 32), 256>>>(Wq, Wkv, Wo);
    // launch 2: latent LayerNorm + A-prep
    ln_prep_kernel<<<(BATCH * NLAT) / 8, 256>>>(latents, ln_lat_g, ln_lat_b, pAq);
    // launch 3 (ncu-captured): kv projection (dominant GEMM)
    kv_mma_kernel<<<dim3(NT, MT), 256, gemm_smem>>>(cosb, sinb);
    // launch 4: q projection
    q_mma_kernel<<<dim3(8, 16), 256, gemm_smem>>>();
    // launch 5: attention -> g_obf
    attn_mma_kernel<<<dim3(NLAT / 128, BH), 256, at_smem_bytes>>>();
    // launch 6: output projection + bias
    o_mma_kernel<<<dim3(8, 16), 256, gemm_smem>>>(bo, out);
}

// round 17
// speedup vs baseline: 1.0565x; 1.0445x over previous
#include <cuda_runtime.h>
#include <cuda_bf16.h>
#include <math.h>
#include <stdint.h>

#define BATCH 8
#define NLAT  256
#define SEQ   4096
#define DIM   1024
#define HEADS 16
#define DHEAD 64
#define INNER 1024
#define EPSLN 1e-5f
#define BH    (BATCH * HEADS)     // 128

// ---- GEMM geometry
#define GM     (BATCH * SEQ)      // 32768
#define GN     (2 * INNER)        // 2048
#define MT     (GM / 128)         // 256 m tiles (kv)
#define NT     (GN / 128)         // 16 n tiles (kv)
#define KCH    (DIM / 64)         // 16 k chunks of 64
#define BLK    16384              // one 128row x 128B swizzled block
#define NSTG   3
#define STG_BYTES (4 * BLK)       // Ah|Al|Bh|Bl = 64KB per stage
#define OFF_STG  1024

// ---------------- scratch (device globals: no runtime allocation) ----------
__device__ uint4 g_A[(size_t)MT * KCH * 2 * BLK / 16];        // 134 MB ctx split-bf16
__device__ uint4 g_B[(size_t)NT * KCH * 2 * BLK / 16];        //   8 MB Wkv split
__device__ uint4 g_Aq[(size_t)16 * KCH * 2 * BLK / 16];       //   8 MB lat split
__device__ uint4 g_Bq[(size_t)8 * KCH * 2 * BLK / 16];        //   4 MB Wq split
__device__ uint4 g_Bo[(size_t)8 * KCH * 2 * BLK / 16];        //   4 MB Wo split
__device__ uint4 g_obf[(size_t)16 * KCH * 2 * BLK / 16];      //   8 MB attn-out split
__device__ uint4 g_qbf[(size_t)BH * 2 * 256 * 128 / 16];      //   8 MB Q hi/lo swizzled
__device__ uint4 g_kbf[(size_t)BH * 64 * 16384 / 16];         // 128 MB K hi/lo (roped)
__device__ uint4 g_vbf[(size_t)BH * 64 * 16384 / 16];         // 128 MB V^T hi/lo

// ---------------- PTX helpers ----------------------------------------------
__device__ __forceinline__ uint32_t smem_u32(const void* p) {
    uint32_t a;
    asm("{ .reg .u64 t; cvta.to.shared.u64 t, %1; cvt.u32.u64 %0, t; }"
        : "=r"(a) : "l"(p));
    return a;
}
__device__ __forceinline__ void mbar_init(uint32_t m, uint32_t cnt) {
    asm volatile("mbarrier.init.shared.b64 [%0], %1;" :: "r"(m), "r"(cnt) : "memory");
}
__device__ __forceinline__ void mbar_expect(uint32_t m, uint32_t bytes) {
    asm volatile("mbarrier.arrive.expect_tx.shared.b64 _, [%0], %1;"
                 :: "r"(m), "r"(bytes) : "memory");
}
__device__ __forceinline__ void mbar_wait(uint32_t m, int ph) {
    asm volatile(
        "{\n\t.reg .pred P;\n\t"
        "W%=:\n\t"
        "mbarrier.try_wait.parity.shared.b64 P, [%0], %1;\n\t"
        "@!P bra W%=;\n\t}"
        :: "r"(m), "r"(ph) : "memory");
}
__device__ __forceinline__ void bulk_g2s(uint32_t dst, const void* src,
                                         uint32_t bytes, uint32_t mbar) {
    asm volatile(
        "cp.async.bulk.shared::cluster.global.mbarrier::complete_tx::bytes "
        "[%0], [%1], %2, [%3];"
        :: "r"(dst), "l"(src), "r"(bytes), "r"(mbar) : "memory");
}
__device__ __forceinline__ void ldmx4(uint32_t* r, uint32_t addr) {
    asm volatile("ldmatrix.sync.aligned.m8n8.x4.shared.b16 {%0,%1,%2,%3}, [%4];"
                 : "=r"(r[0]), "=r"(r[1]), "=r"(r[2]), "=r"(r[3]) : "r"(addr));
}
__device__ __forceinline__ void mma16816(float* c, const uint32_t* a,
                                         uint32_t b0, uint32_t b1) {
    asm volatile(
        "mma.sync.aligned.m16n8k16.row.col.f32.bf16.bf16.f32 "
        "{%0,%1,%2,%3}, {%4,%5,%6,%7}, {%8,%9}, {%0,%1,%2,%3};"
        : "+f"(c[0]), "+f"(c[1]), "+f"(c[2]), "+f"(c[3])
        : "r"(a[0]), "r"(a[1]), "r"(a[2]), "r"(a[3]), "r"(b0), "r"(b1));
}
__device__ __forceinline__ void split2(float a, float b, uint32_t& hi, uint32_t& lo) {
    __nv_bfloat16 ha = __float2bfloat16(a), hb = __float2bfloat16(b);
    float ra = a - __bfloat162float(ha), rb = b - __bfloat162float(hb);
    __nv_bfloat16 la = __float2bfloat16(ra), lb = __float2bfloat16(rb);
    hi = (uint32_t)__bfloat16_as_ushort(ha) | ((uint32_t)__bfloat16_as_ushort(hb) << 16);
    lo = (uint32_t)__bfloat16_as_ushort(la) | ((uint32_t)__bfloat16_as_ushort(lb) << 16);
}

// ---------------- shared split-bf16 mma mainloop ----------------------------
extern __shared__ char dyn_smem[];

__device__ __forceinline__ void mma_tile_mainloop(
    const char* __restrict__ Ab, const char* __restrict__ Bb, const int kch,
    const uint32_t sb, float (&acc)[2][8][4])
{
    const int t = threadIdx.x;
    const int w = t >> 5, lane = t & 31;
    const int wm = w & 3, wn = w >> 2;          // 4 x 2 warp grid

    if (t == 0) {
        #pragma unroll
        for (int i = 0; i < NSTG; i++) mbar_init(sb + 8 * i, 1);
    }
    __syncthreads();
    asm volatile("fence.proxy.async.shared::cta;" ::: "memory");

    if (t == 0) {
        #pragma unroll
        for (int c = 0; c < NSTG; c++) {
            uint32_t st = sb + OFF_STG + c * STG_BYTES;
            mbar_expect(sb + 8 * c, STG_BYTES);
            bulk_g2s(st,           Ab + (size_t)c * 2 * BLK, 2 * BLK, sb + 8 * c);
            bulk_g2s(st + 2 * BLK, Bb + (size_t)c * 2 * BLK, 2 * BLK, sb + 8 * c);
        }
    }

    const int l15 = lane & 15;
    const uint32_t kb16 = (uint32_t)(lane & 16);
    const uint32_t mask = (uint32_t)((lane & 7) << 4);
    uint32_t aoff[2], boff[4];
    #pragma unroll
    for (int mi = 0; mi < 2; mi++) aoff[mi] = (uint32_t)((wm * 32 + mi * 16 + l15) * 128);
    #pragma unroll
    for (int p = 0; p < 4; p++)    boff[p]  = (uint32_t)((wn * 64 + p * 16 + l15) * 128);

    #pragma unroll
    for (int mi = 0; mi < 2; mi++)
        #pragma unroll
        for (int ni = 0; ni < 8; ni++)
            #pragma unroll
            for (int q = 0; q < 4; q++) acc[mi][ni][q] = 0.f;

    int ph[NSTG] = {0, 0, 0};

    for (int kc = 0; kc < kch; kc++) {
        const int s = kc % NSTG;
        mbar_wait(sb + 8 * s, ph[s]); ph[s] ^= 1;
        const uint32_t base = sb + OFF_STG + s * STG_BYTES;

        #pragma unroll
        for (int ks = 0; ks < 4; ks++) {
            const uint32_t kx = ((uint32_t)(ks * 32) + kb16) ^ mask;
            uint32_t ah[2][4], al[2][4], bh[4][4], bl[4][4];
            #pragma unroll
            for (int mi = 0; mi < 2; mi++) {
                ldmx4(ah[mi], base + aoff[mi] + kx);
                ldmx4(al[mi], base + BLK + aoff[mi] + kx);
            }
            #pragma unroll
            for (int p = 0; p < 4; p++) {
                ldmx4(bh[p], base + 2 * BLK + boff[p] + kx);
                ldmx4(bl[p], base + 3 * BLK + boff[p] + kx);
            }
            #pragma unroll
            for (int mi = 0; mi < 2; mi++)
                #pragma unroll
                for (int p = 0; p < 4; p++) {
                    mma16816(acc[mi][2 * p + 0], ah[mi], bh[p][0], bh[p][2]);
                    mma16816(acc[mi][2 * p + 1], ah[mi], bh[p][1], bh[p][3]);
                }
            #pragma unroll
            for (int mi = 0; mi < 2; mi++)
                #pragma unroll
                for (int p = 0; p < 4; p++) {
                    mma16816(acc[mi][2 * p + 0], ah[mi], bl[p][0], bl[p][2]);
                    mma16816(acc[mi][2 * p + 1], ah[mi], bl[p][1], bl[p][3]);
                }
            #pragma unroll
            for (int mi = 0; mi < 2; mi++)
                #pragma unroll
                for (int p = 0; p < 4; p++) {
                    mma16816(acc[mi][2 * p + 0], al[mi], bh[p][0], bh[p][2]);
                    mma16816(acc[mi][2 * p + 1], al[mi], bh[p][1], bh[p][3]);
                }
        }
        __syncthreads();
        const int nxt = kc + NSTG;
        if (t == 0 && nxt < kch) {
            mbar_expect(sb + 8 * s, STG_BYTES);
            bulk_g2s(base,           Ab + (size_t)nxt * 2 * BLK, 2 * BLK, sb + 8 * s);
            bulk_g2s(base + 2 * BLK, Bb + (size_t)nxt * 2 * BLK, 2 * BLK, sb + 8 * s);
        }
    }
}

// -------- LayerNorm (warp-per-row) fused with split-bf16 A-prep -------------
__global__ __launch_bounds__(256) void ln_prep_kernel(
    const float* __restrict__ x, const float* __restrict__ gam,
    const float* __restrict__ bet, uint4* __restrict__ dstb)
{
    const int wid = threadIdx.x >> 5, lane = threadIdx.x & 31;
    const int row = blockIdx.x * 8 + wid;
    const float4* xr = (const float4*)(x + (size_t)row * DIM);

    float4 v[8];
    float s = 0.f;
    #pragma unroll
    for (int i = 0; i < 8; i++) {
        v[i] = xr[i * 32 + lane];
        s += v[i].x + v[i].y + v[i].z + v[i].w;
    }
    #pragma unroll
    for (int off = 16; off; off >>= 1) s += __shfl_xor_sync(0xffffffffu, s, off);
    const float mu = s * (1.0f / DIM);

    float s2 = 0.f;
    #pragma unroll
    for (int i = 0; i < 8; i++) {
        v[i].x -= mu; v[i].y -= mu; v[i].z -= mu; v[i].w -= mu;
        s2 += v[i].x * v[i].x + v[i].y * v[i].y + v[i].z * v[i].z + v[i].w * v[i].w;
    }
    #pragma unroll
    for (int off = 16; off; off >>= 1) s2 += __shfl_xor_sync(0xffffffffu, s2, off);
    const float rs = rsqrtf(s2 * (1.0f / DIM) + EPSLN);

    const int mt = row >> 7, r = row & 127;
    char* dst0 = (char*)dstb + (size_t)(mt * KCH) * 2 * BLK;
    #pragma unroll
    for (int i = 0; i < 8; i++) {
        const int slot = i * 32 + lane;          // float4 slot 0..255
        const float4 gg = ((const float4*)gam)[slot];
        const float4 bb = ((const float4*)bet)[slot];
        const float o0 = v[i].x * rs * gg.x + bb.x;
        const float o1 = v[i].y * rs * gg.y + bb.y;
        const float o2 = v[i].z * rs * gg.z + bb.z;
        const float o3 = v[i].w * rs * gg.w + bb.w;
        uint32_t h0, l0, h1, l1;
        split2(o0, o1, h0, l0);
        split2(o2, o3, h1, l1);
        const int chunk = slot >> 4;
        const int c = (slot & 15) * 4;
        uint32_t bo = (uint32_t)(r * 128 + c * 2);
        uint32_t sw = bo ^ ((bo >> 3) & 0x70);
        char* dst = dst0 + (size_t)chunk * 2 * BLK + sw;
        *(uint2*)dst = make_uint2(h0, h1);
        *(uint2*)(dst + BLK) = make_uint2(l0, l1);
    }
}

// -------- all 3 weight preps in one launch: grid (KCH, 32) ------------------
__global__ __launch_bounds__(256) void wprep_all_kernel(
    const float* __restrict__ Wq, const float* __restrict__ Wkv,
    const float* __restrict__ Wo)
{
    __shared__ float ws[64][132];     // 132-float pitch: 528B = 33x16, aligned
    const int by = blockIdx.y;
    const float* W;
    uint4* dstb;
    int N, nt;
    if (by < 8)       { W = Wq;  dstb = g_Bq; N = INNER; nt = by; }
    else if (by < 24) { W = Wkv; dstb = g_B;  N = GN;    nt = by - 8; }
    else              { W = Wo;  dstb = g_Bo; N = DIM;   nt = by - 24; }

    const int chunk = blockIdx.x;     // 0..15 (64 k-values each)
    const int t = threadIdx.x;
    {
        const int rr = t >> 5;        // 0..7
        const int cc = (t & 31) * 4;
        #pragma unroll
        for (int i = 0; i < 8; i++) {
            const int k = chunk * 64 + rr + i * 8;
            *(float4*)&ws[rr + i * 8][cc] =
                *(const float4*)&W[(size_t)k * N + nt * 128 + cc];
        }
    }
    __syncthreads();
    const int n = t & 127, sel = t >> 7;
    char* dst = (char*)dstb + ((size_t)(nt * KCH + chunk) * 2) * BLK + sel * BLK;
    #pragma unroll
    for (int j = 0; j < 8; j++) {
        uint32_t outv[4];
        #pragma unroll
        for (int kk = 0; kk < 4; kk++) {
            const int k2 = j * 8 + kk * 2;
            uint32_t hi, lo;
            split2(ws[k2][n], ws[k2 + 1][n], hi, lo);
            outv[kk] = sel ? lo : hi;
        }
        uint32_t bo = (uint32_t)(n * 128 + 16 * j);
        uint32_t sw = bo ^ ((bo >> 3) & 0x70);
        *(uint4*)(dst + sw) = make_uint4(outv[0], outv[1], outv[2], outv[3]);
    }
}

// -------- kv GEMM: fused epilogue -> g_kbf (RoPE) / g_vbf (transpose) -------
__global__ __launch_bounds__(256) void kv_mma_kernel(
    const float* __restrict__ cosb, const float* __restrict__ sinb)
{
    const uint32_t sb = smem_u32(dyn_smem);
    const int t = threadIdx.x, w = t >> 5, lane = t & 31;
    const int wm = w & 3, wn = w >> 2, g = lane >> 2, tig = lane & 3;
    const int bx = blockIdx.x, by = blockIdx.y;

    float acc[2][8][4];
    mma_tile_mainloop((const char*)g_A + (size_t)by * KCH * 2 * BLK,
                      (const char*)g_B + (size_t)bx * KCH * 2 * BLK, KCH, sb, acc);

    if (bx < 8) {
        // ---- K columns: RoPE in registers, write g_kbf swizzled hi/lo ----
        const int h = bx * 2 + wn;
        #pragma unroll
        for (int mi = 0; mi < 2; mi++) {
            const int row0 = by * 128 + wm * 32 + mi * 16 + g;
            const int b = row0 >> 12;
            #pragma unroll
            for (int qq = 0; qq < 2; qq++) {
                const int s = (row0 & 4095) + 8 * qq;
                char* dst = (char*)g_kbf +
                            ((size_t)((b * 16 + h) * 64 + (s >> 6))) * 16384;
                const int r = s & 63;
                const float2* cb  = (const float2*)&cosb[s * 32];
                const float2* sb2 = (const float2*)&sinb[s * 32];
                #pragma unroll
                for (int ni = 0; ni < 4; ni++) {
                    const int d0 = ni * 8 + tig * 2;   // 0..30, partner d0+32
                    const float k1a = acc[mi][ni][2 * qq];
                    const float k1b = acc[mi][ni][2 * qq + 1];
                    const float k2a = acc[mi][ni + 4][2 * qq];
                    const float k2b = acc[mi][ni + 4][2 * qq + 1];
                    const float2 c  = cb[d0 >> 1];
                    const float2 sn = sb2[d0 >> 1];
                    uint32_t hi, lo;
                    split2(k1a * c.x - k2a * sn.x, k1b * c.y - k2b * sn.y, hi, lo);
                    uint32_t bo = (uint32_t)(r * 128 + 2 * d0);
                    uint32_t sw = bo ^ ((bo >> 3) & 0x70);
                    *(uint32_t*)(dst + sw) = hi;
                    *(uint32_t*)(dst + 8192 + sw) = lo;
                    split2(k2a * c.x + k1a * sn.x, k2b * c.y + k1b * sn.y, hi, lo);
                    uint32_t bo2 = bo + 64;            // d0+32
                    uint32_t sw2 = bo2 ^ ((bo2 >> 3) & 0x70);
                    *(uint32_t*)(dst + sw2) = hi;
                    *(uint32_t*)(dst + 8192 + sw2) = lo;
                }
            }
        }
    } else {
        // ---- V columns: smem transpose (stage smem is free) -> g_vbf -------
        unsigned short* VH = (unsigned short*)(dyn_smem + OFF_STG);
        unsigned short* VL = VH + 128 * 136;   // 136-ushort pitch (272B = 17x16)
        #pragma unroll
        for (int mi = 0; mi < 2; mi++)
            #pragma unroll
            for (int ni = 0; ni < 8; ni++)
                #pragma unroll
                for (int q = 0; q < 4; q++) {
                    const int d = wn * 64 + ni * 8 + tig * 2 + (q & 1);
                    const int srow = wm * 32 + mi * 16 + g + 8 * (q >> 1);
                    const float v = acc[mi][ni][q];
                    const __nv_bfloat16 hb = __float2bfloat16(v);
                    const __nv_bfloat16 lb =
                        __float2bfloat16(v - __bfloat162float(hb));
                    VH[d * 136 + srow] = __bfloat16_as_ushort(hb);
                    VL[d * 136 + srow] = __bfloat16_as_ushort(lb);
                }
        __syncthreads();
        const int c = t & 127, sel = t >> 7;
        const int head = (bx - 8) * 2 + (c >> 6);
        const int dd = c & 63;
        const int b = by >> 5;
        const int scb = (by & 31) * 2;
        const unsigned short* src = (sel ? VL : VH) + c * 136;
        #pragma unroll
        for (int blk8 = 0; blk8 < 16; blk8++) {
            const uint4 v = *(const uint4*)(src + blk8 * 8);
            char* dst = (char*)g_vbf +
                        ((size_t)((b * 16 + head) * 64 + scb + (blk8 >> 3))) * 16384 +
                        sel * 8192;
            uint32_t bo = (uint32_t)(dd * 128 + 16 * (blk8 & 7));
            uint32_t sw = bo ^ ((bo >> 3) & 0x70);
            *(uint4*)(dst + sw) = v;
        }
    }
}

// -------- q GEMM: epilogue (x0.125 folded) -> g_qbf -------------------------
__global__ __launch_bounds__(256) void q_mma_kernel()
{
    const uint32_t sb = smem_u32(dyn_smem);
    const int t = threadIdx.x, w = t >> 5, lane = t & 31;
    const int wm = w & 3, wn = w >> 2, g = lane >> 2, tig = lane & 3;
    const int bx = blockIdx.x, by = blockIdx.y;   // bx 0..7, by 0..15

    float acc[2][8][4];
    mma_tile_mainloop((const char*)g_Aq + (size_t)by * KCH * 2 * BLK,
                      (const char*)g_Bq + (size_t)bx * KCH * 2 * BLK, KCH, sb, acc);

    const int h = bx * 2 + wn;
    #pragma unroll
    for (int mi = 0; mi < 2; mi++) {
        const int grow = by * 128 + wm * 32 + mi * 16 + g;
        const int b = grow >> 8, n = grow & 255;
        char* base = (char*)g_qbf + (size_t)(b * 16 + h) * 65536;
        #pragma unroll
        for (int ni = 0; ni < 8; ni++) {
            uint32_t hi, lo;
            split2(acc[mi][ni][0] * 0.125f, acc[mi][ni][1] * 0.125f, hi, lo);
            uint32_t bo = (uint32_t)(n * 128 + 16 * ni + 4 * tig);
            uint32_t sw = bo ^ ((bo >> 3) & 0x70);
            *(uint32_t*)(base + sw) = hi;
            *(uint32_t*)(base + 32768 + sw) = lo;
            split2(acc[mi][ni][2] * 0.125f, acc[mi][ni][3] * 0.125f, hi, lo);
            uint32_t bo2 = (uint32_t)((n + 8) * 128 + 16 * ni + 4 * tig);
            uint32_t sw2 = bo2 ^ ((bo2 >> 3) & 0x70);
            *(uint32_t*)(base + sw2) = hi;
            *(uint32_t*)(base + 32768 + sw2) = lo;
        }
    }
}

// -------- o GEMM: A = g_obf (attn out), epilogue -> out fp32 + bias ---------
__global__ __launch_bounds__(256) void o_mma_kernel(
    const float* __restrict__ bias, float* __restrict__ out)
{
    const uint32_t sb = smem_u32(dyn_smem);
    const int t = threadIdx.x, w = t >> 5, lane = t & 31;
    const int wm = w & 3, wn = w >> 2, g = lane >> 2, tig = lane & 3;
    const int bx = blockIdx.x, by = blockIdx.y;   // bx 0..7, by 0..15

    float acc[2][8][4];
    mma_tile_mainloop((const char*)g_obf + (size_t)by * KCH * 2 * BLK,
                      (const char*)g_Bo + (size_t)bx * KCH * 2 * BLK, KCH, sb, acc);

    #pragma unroll
    for (int mi = 0; mi < 2; mi++) {
        const int row0 = by * 128 + wm * 32 + mi * 16 + g;
        #pragma unroll
        for (int ni = 0; ni < 8; ni++) {
            const int col = bx * 128 + wn * 64 + ni * 8 + tig * 2;
            const float2 bb = *(const float2*)&bias[col];
            *(float2*)&out[(size_t)row0 * DIM + col] =
                make_float2(acc[mi][ni][0] + bb.x, acc[mi][ni][1] + bb.y);
            *(float2*)&out[(size_t)(row0 + 8) * DIM + col] =
                make_float2(acc[mi][ni][2] + bb.x, acc[mi][ni][3] + bb.y);
        }
    }
}

// -------- Flash attention: one CTA per (b,h), both q-tiles share KV ---------
#define ACH 32768      // per stage: K(hi|lo 16KB) + V(hi|lo 16KB)
#define AQB 65536      // resident Q: hi 32KB + lo 32KB (256 rows)

__global__ __launch_bounds__(256) void attn_mma_kernel()
{
    const uint32_t sb = smem_u32(dyn_smem);
    const int t = threadIdx.x, w = t >> 5, lane = t & 31;
    const int bh = blockIdx.x;
    const int b = bh >> 4, h = bh & 15;
    const int g = lane >> 2, tig = lane & 3;
    const int l15 = lane & 15;
    const uint32_t kb16 = (uint32_t)(lane & 16);
    const uint32_t mask = (uint32_t)((lane & 7) << 4);
    const uint32_t stq = sb + 64;          // Q hi|lo, resident
    const uint32_t stg = stq + AQB;        // 2 KV stages

    if (t == 0) { mbar_init(sb, 1); mbar_init(sb + 8, 1); mbar_init(sb + 16, 1); }
    __syncthreads();
    asm volatile("fence.proxy.async.shared::cta;" ::: "memory");

    const char* Qg = (const char*)g_qbf + (size_t)bh * 65536;
    const char* Kg = (const char*)g_kbf + (size_t)bh * 64 * 16384;
    const char* Vg = (const char*)g_vbf + (size_t)bh * 64 * 16384;
    if (t == 0) {
        mbar_expect(sb + 16, AQB);
        bulk_g2s(stq, Qg, AQB, sb + 16);
        #pragma unroll
        for (int c = 0; c < 2; c++) {
            mbar_expect(sb + 8 * c, 32768);
            bulk_g2s(stg + c * ACH,         Kg + (size_t)c * 16384, 16384, sb + 8 * c);
            bulk_g2s(stg + c * ACH + 16384, Vg + (size_t)c * 16384, 16384, sb + 8 * c);
        }
    }
    mbar_wait(sb + 16, 0);   // Q resident
    int ph0 = 0, ph1 = 0;

    // fixed max = 11 (logits clipped to [-11,11]): exp(s-11), plain accumulation
    float lA[2] = {0.f, 0.f}, lB[2] = {0.f, 0.f};
    float o[2][8][4];
    #pragma unroll
    for (int qt = 0; qt < 2; qt++)
        #pragma unroll
        for (int ni = 0; ni < 8; ni++)
            #pragma unroll
            for (int q = 0; q < 4; q++) o[qt][ni][q] = 0.f;

    const uint32_t qro = (uint32_t)((w * 16 + l15) * 128);

    for (int sc = 0; sc < 64; sc++) {
        const int s = sc & 1;
        if (s == 0) { mbar_wait(sb, ph0); ph0 ^= 1; }
        else        { mbar_wait(sb + 8, ph1); ph1 ^= 1; }
        const uint32_t kb = stg + s * ACH;
        const uint32_t vb = kb + 16384;

        float sacc[2][8][4];
        #pragma unroll
        for (int qt = 0; qt < 2; qt++)
            #pragma unroll
            for (int ni = 0; ni < 8; ni++)
                #pragma unroll
                for (int q = 0; q < 4; q++) sacc[qt][ni][q] = 0.f;

        // S = Q K^T: K frags loaded once, shared by both q-tiles
        #pragma unroll
        for (int ks = 0; ks < 4; ks++) {
            const uint32_t kx = ((uint32_t)(ks * 32) + kb16) ^ mask;
            uint32_t qh[2][4], ql[2][4];
            #pragma unroll
            for (int qt = 0; qt < 2; qt++) {
                ldmx4(qh[qt], stq + qro + qt * 16384 + kx);
                ldmx4(ql[qt], stq + 32768 + qro + qt * 16384 + kx);
            }
            #pragma unroll
            for (int p = 0; p < 4; p++) {
                uint32_t kh[4], kl[4];
                const uint32_t ro = (uint32_t)((p * 16 + l15) * 128);
                ldmx4(kh, kb + ro + kx);
                ldmx4(kl, kb + 8192 + ro + kx);
                #pragma unroll
                for (int qt = 0; qt < 2; qt++) {
                    mma16816(sacc[qt][2 * p + 0], qh[qt], kh[0], kh[2]);
                    mma16816(sacc[qt][2 * p + 1], qh[qt], kh[1], kh[3]);
                    mma16816(sacc[qt][2 * p + 0], qh[qt], kl[0], kl[2]);
                    mma16816(sacc[qt][2 * p + 1], qh[qt], kl[1], kl[3]);
                    mma16816(sacc[qt][2 * p + 0], ql[qt], kh[0], kh[2]);
                    mma16816(sacc[qt][2 * p + 1], ql[qt], kh[1], kh[3]);
                }
            }
        }

        // p = exp(clip(s) - 11); accumulate row sums
        #pragma unroll
        for (int qt = 0; qt < 2; qt++)
            #pragma unroll
            for (int ni = 0; ni < 8; ni++) {
                sacc[qt][ni][0] = __expf(fminf(0.f, fmaxf(-22.f, sacc[qt][ni][0] - 11.f)));
                sacc[qt][ni][1] = __expf(fminf(0.f, fmaxf(-22.f, sacc[qt][ni][1] - 11.f)));
                sacc[qt][ni][2] = __expf(fminf(0.f, fmaxf(-22.f, sacc[qt][ni][2] - 11.f)));
                sacc[qt][ni][3] = __expf(fminf(0.f, fmaxf(-22.f, sacc[qt][ni][3] - 11.f)));
                lA[qt] += sacc[qt][ni][0] + sacc[qt][ni][1];
                lB[qt] += sacc[qt][ni][2] + sacc[qt][ni][3];
            }

        // O += P V: V frags loaded once, shared by both q-tiles
        #pragma unroll
        for (int ks = 0; ks < 4; ks++) {
            uint32_t pah[2][4], pal[2][4];
            #pragma unroll
            for (int qt = 0; qt < 2; qt++) {
                split2(sacc[qt][2 * ks][0],     sacc[qt][2 * ks][1],     pah[qt][0], pal[qt][0]);
                split2(sacc[qt][2 * ks][2],     sacc[qt][2 * ks][3],     pah[qt][1], pal[qt][1]);
                split2(sacc[qt][2 * ks + 1][0], sacc[qt][2 * ks + 1][1], pah[qt][2], pal[qt][2]);
                split2(sacc[qt][2 * ks + 1][2], sacc[qt][2 * ks + 1][3], pah[qt][3], pal[qt][3]);
            }
            const uint32_t kx = ((uint32_t)(ks * 32) + kb16) ^ mask;
            #pragma unroll
            for (int p = 0; p < 4; p++) {
                uint32_t vh[4], vl[4];
                const uint32_t ro = (uint32_t)((p * 16 + l15) * 128);
                ldmx4(vh, vb + ro + kx);
                ldmx4(vl, vb + 8192 + ro + kx);
                #pragma unroll
                for (int qt = 0; qt < 2; qt++) {
                    mma16816(o[qt][2 * p + 0], pah[qt], vh[0], vh[2]);
                    mma16816(o[qt][2 * p + 1], pah[qt], vh[1], vh[3]);
                    mma16816(o[qt][2 * p + 0], pah[qt], vl[0], vl[2]);
                    mma16816(o[qt][2 * p + 1], pah[qt], vl[1], vl[3]);
                    mma16816(o[qt][2 * p + 0], pal[qt], vh[0], vh[2]);
                    mma16816(o[qt][2 * p + 1], pal[qt], vh[1], vh[3]);
                }
            }
        }
        __syncthreads();
        if (t == 0 && sc + 2 < 64) {
            const int nc = sc + 2;
            const uint32_t dst = stg + s * ACH;
            mbar_expect(sb + 8 * s, 32768);
            bulk_g2s(dst,         Kg + (size_t)nc * 16384, 16384, sb + 8 * s);
            bulk_g2s(dst + 16384, Vg + (size_t)nc * 16384, 16384, sb + 8 * s);
        }
    }

    // finalize: quad-reduce row sums, normalize, write split-bf16 to g_obf
    #pragma unroll
    for (int qt = 0; qt < 2; qt++) {
        float la = lA[qt], lb2 = lB[qt];
        la += __shfl_xor_sync(0xffffffffu, la, 1);
        la += __shfl_xor_sync(0xffffffffu, la, 2);
        lb2 += __shfl_xor_sync(0xffffffffu, lb2, 1);
        lb2 += __shfl_xor_sync(0xffffffffu, lb2, 2);
        const float iA = 1.f / la, iB = 1.f / lb2;
        const int growA = b * NLAT + qt * 128 + w * 16 + g;
        const int mt = growA >> 7;
        char* ob = (char*)g_obf + ((size_t)(mt * KCH + h) * 2) * BLK;
        const int rA = growA & 127;
        #pragma unroll
        for (int ni = 0; ni < 8; ni++) {
            uint32_t hi, lo;
            split2(o[qt][ni][0] * iA, o[qt][ni][1] * iA, hi, lo);
            uint32_t bo = (uint32_t)(rA * 128 + 16 * ni + 4 * tig);
            uint32_t sw = bo ^ ((bo >> 3) & 0x70);
            *(uint32_t*)(ob + sw) = hi;
            *(uint32_t*)(ob + BLK + sw) = lo;
            split2(o[qt][ni][2] * iB, o[qt][ni][3] * iB, hi, lo);
            uint32_t bo2 = (uint32_t)((rA + 8) * 128 + 16 * ni + 4 * tig);
            uint32_t sw2 = bo2 ^ ((bo2 >> 3) & 0x70);
            *(uint32_t*)(ob + sw2) = hi;
            *(uint32_t*)(ob + BLK + sw2) = lo;
        }
    }
}

// ---------------- host launcher --------------------------------------------
extern "C" void kernel_launch(void* const* d_in, const int* in_sizes, int n_in,
                              void* d_out, int out_size)
{
    const float* latents  = (const float*)d_in[0];
    const float* context  = (const float*)d_in[1];
    const float* cosb     = (const float*)d_in[2];
    const float* sinb     = (const float*)d_in[3];
    const float* ln_lat_g = (const float*)d_in[4];
    const float* ln_lat_b = (const float*)d_in[5];
    const float* ln_ctx_g = (const float*)d_in[6];
    const float* ln_ctx_b = (const float*)d_in[7];
    const float* Wq       = (const float*)d_in[8];
    const float* Wkv      = (const float*)d_in[9];
    const float* Wo       = (const float*)d_in[10];
    const float* bo       = (const float*)d_in[11];
    float* out = (float*)d_out;

    uint4 *pAq, *pA;
    cudaGetSymbolAddress((void**)&pAq, g_Aq);
    cudaGetSymbolAddress((void**)&pA,  g_A);

    const int gemm_smem = OFF_STG + NSTG * STG_BYTES;   // 197632
    cudaFuncSetAttribute(kv_mma_kernel, cudaFuncAttributeMaxDynamicSharedMemorySize, gemm_smem);
    cudaFuncSetAttribute(q_mma_kernel,  cudaFuncAttributeMaxDynamicSharedMemorySize, gemm_smem);
    cudaFuncSetAttribute(o_mma_kernel,  cudaFuncAttributeMaxDynamicSharedMemorySize, gemm_smem);
    const int at_smem_bytes = 64 + AQB + 2 * ACH;   // 131136
    cudaFuncSetAttribute(attn_mma_kernel, cudaFuncAttributeMaxDynamicSharedMemorySize, at_smem_bytes);

    // launch 0: ctx LayerNorm + A-prep
    ln_prep_kernel<<<(BATCH * SEQ) / 8, 256>>>(context, ln_ctx_g, ln_ctx_b, pA);
    // launch 1: all weight preps
    wprep_all_kernel<<<dim3(KCH, 32), 256>>>(Wq, Wkv, Wo);
    // launch 2: latent LayerNorm + A-prep
    ln_prep_kernel<<<(BATCH * NLAT) / 8, 256>>>(latents, ln_lat_g, ln_lat_b, pAq);
    // launch 3 (ncu-captured): kv projection (dominant GEMM)
    kv_mma_kernel<<<dim3(NT, MT), 256, gemm_smem>>>(cosb, sinb);
    // launch 4: q projection
    q_mma_kernel<<<dim3(8, 16), 256, gemm_smem>>>();
    // launch 5: attention -> g_obf (one CTA per (b,h))
    attn_mma_kernel<<<BH, 256, at_smem_bytes>>>();
    // launch 6: output projection + bias
    o_mma_kernel<<<dim3(8, 16), 256, gemm_smem>>>(bo, out);
}